// round 12
// baseline (speedup 1.0000x reference)
#include <cuda_runtime.h>
#include <cuda_fp16.h>
#include <cuda_bf16.h>
#include <math.h>
#include <stdint.h>

#define BB 8
#define NN 2048
#define EE 64
#define DD 256
#define ROWS (BB*NN)   // 16384

// ---------------- scratch (static device globals; no allocs) ----------------
__device__ __align__(16) __half g_xh[ROWS*EE];   // LN(x) in fp16
__device__ __align__(16) __half g_q[ROWS*DD];
__device__ __align__(16) __half g_k[ROWS*DD];
__device__ __align__(16) __half g_vo[ROWS*EE];   // V @ ow^T (+ ow@wvb), fp16, 64-wide
// per-head masked weighted exponents, bf16, A-fragment-major:
// [rowblock16 0..1023][keyblock16-in-batch 0..127][head 0..3][lane 0..31] uint4
__device__ uint4 g_e[(size_t)1024*128*4*32];   // 256MB
__device__ float4 g_il[ROWS];                  // 1/l per head
__device__ float  g_z[ROWS];                   // 1/z
__device__ float g_av[ROWS*EE];                // (C @ Vo)/z, 64-wide fp32
__device__ __align__(16) __half g_Wh[768*64];  // folded weights (q,k rows 0-511; Wvo 512-575; 0 pad)
__device__ float g_bp[768];

#define CEXP 0.18033688f   // 0.125 * log2(e)

// ---------------- generic helpers ----------------
__device__ __forceinline__ float wsum(float v){
    v += __shfl_xor_sync(0xffffffffu, v, 16);
    v += __shfl_xor_sync(0xffffffffu, v, 8);
    v += __shfl_xor_sync(0xffffffffu, v, 4);
    v += __shfl_xor_sync(0xffffffffu, v, 2);
    v += __shfl_xor_sync(0xffffffffu, v, 1);
    return v;
}
__device__ __forceinline__ float softplusf(float x){
    if (x > 20.f) return x;
    return log1pf(expf(x));
}
__device__ __forceinline__ uint32_t smem_u32(const void* p){
    uint32_t a;
    asm("{ .reg .u64 t; cvta.to.shared.u64 t, %1; cvt.u32.u64 %0, t; }" : "=r"(a) : "l"(p));
    return a;
}
__device__ __forceinline__ float ex2f(float x){
    float r;
    asm("ex2.approx.f32 %0, %1;" : "=f"(r) : "f"(x));
    return r;
}
__device__ __forceinline__ uint32_t packbf2(float a, float b){
    __nv_bfloat162 h = __floats2bfloat162_rn(a, b);
    return *(uint32_t*)&h;
}
__device__ __forceinline__ float bflo(uint32_t u){ return __uint_as_float(u << 16); }
__device__ __forceinline__ float bfhi(uint32_t u){ return __uint_as_float(u & 0xFFFF0000u); }

// ---------------- cp.async helpers (sm_80+ baseline) ----------------
__device__ __forceinline__ void cpa16(uint32_t dst, const void* src){
    asm volatile("cp.async.cg.shared.global [%0], [%1], 16;" :: "r"(dst), "l"(src) : "memory");
}
__device__ __forceinline__ void cpa4(uint32_t dst, const void* src){
    asm volatile("cp.async.ca.shared.global [%0], [%1], 4;" :: "r"(dst), "l"(src) : "memory");
}
#define CPA_COMMIT() asm volatile("cp.async.commit_group;" ::: "memory")
#define CPA_WAIT(n)  asm volatile("cp.async.wait_group %0;" :: "n"(n) : "memory")

// ---------------- mma.sync / ldmatrix helpers (baseline PTX, sm_80+) --------
__device__ __forceinline__ void ldm_x4(uint32_t a[4], uint32_t addr){
    asm volatile("ldmatrix.sync.aligned.m8n8.x4.shared.b16 {%0,%1,%2,%3}, [%4];"
        : "=r"(a[0]), "=r"(a[1]), "=r"(a[2]), "=r"(a[3]) : "r"(addr));
}
__device__ __forceinline__ void ldm_x4t(uint32_t a[4], uint32_t addr){
    asm volatile("ldmatrix.sync.aligned.m8n8.x4.trans.shared.b16 {%0,%1,%2,%3}, [%4];"
        : "=r"(a[0]), "=r"(a[1]), "=r"(a[2]), "=r"(a[3]) : "r"(addr));
}
__device__ __forceinline__ void mma16816(float c[4], const uint32_t a[4], const uint32_t b[2]){
    asm volatile("mma.sync.aligned.m16n8k16.row.col.f32.f16.f16.f32 "
        "{%0,%1,%2,%3}, {%4,%5,%6,%7}, {%8,%9}, {%0,%1,%2,%3};"
        : "+f"(c[0]), "+f"(c[1]), "+f"(c[2]), "+f"(c[3])
        : "r"(a[0]), "r"(a[1]), "r"(a[2]), "r"(a[3]), "r"(b[0]), "r"(b[1]));
}

// ---------------- fold: q/k effective weights + Wvo = ow @ wv ---------------
__global__ void k_fold(const float* __restrict__ wq_w, const float* __restrict__ wq_b,
                       const float* __restrict__ wk_w, const float* __restrict__ wk_b,
                       const float* __restrict__ wv_w, const float* __restrict__ wv_b,
                       const float* __restrict__ mq_w, const float* __restrict__ mq_b,
                       const float* __restrict__ mk_w, const float* __restrict__ mk_b,
                       const float* __restrict__ ow){
    int r = blockIdx.x, e = threadIdx.x;
    if (r < 256){
        float acc = 0.f;
        for (int c = 0; c < 256; c++) acc += mq_w[r*256+c]*wq_w[c*64+e];
        g_Wh[r*64+e] = __float2half_rn(acc);
        if (e == 0){
            float bb = mq_b[r];
            for (int c = 0; c < 256; c++) bb += mq_w[r*256+c]*wq_b[c];
            g_bp[r] = bb;
        }
    } else if (r < 512){
        int rr = r - 256;
        float acc = 0.f;
        for (int c = 0; c < 256; c++) acc += mk_w[rr*256+c]*wk_w[c*64+e];
        g_Wh[r*64+e] = __float2half_rn(acc);
        if (e == 0){
            float bb = mk_b[rr];
            for (int c = 0; c < 256; c++) bb += mk_w[rr*256+c]*wk_b[c];
            g_bp[r] = bb;
        }
    } else if (r < 576){
        int rr = r - 512;   // Wvo[rr][e] = sum_d ow[rr][d] * wv_w[d][e]
        float acc = 0.f;
        for (int d = 0; d < 256; d++) acc += ow[rr*256+d]*wv_w[d*64+e];
        g_Wh[r*64+e] = __float2half_rn(acc);
        if (e == 0){
            float bb = 0.f;
            for (int d = 0; d < 256; d++) bb += ow[rr*256+d]*wv_b[d];
            g_bp[r] = bb;
        }
    } else {
        g_Wh[r*64+e] = __float2half_rn(0.f);
        if (e == 0) g_bp[r] = 0.f;
    }
}

// ---------------- LayerNorm over E=64 -> fp16: one warp per row --------------
__global__ __launch_bounds__(256) void k_ln(const float* __restrict__ x,
                                            const float* __restrict__ g,
                                            const float* __restrict__ be){
    int t = threadIdx.x, lane = t & 31, w = t >> 5;
    size_t row = (size_t)blockIdx.x*8 + w;
    const float* xr = x + row*64;
    float x0 = xr[lane], x1 = xr[lane+32];
    float mean = wsum(x0+x1)*(1.f/64.f);
    float msq  = wsum(x0*x0+x1*x1)*(1.f/64.f);
    float rs = rsqrtf(msq - mean*mean + 1e-5f);
    __half* o = g_xh + row*64;
    o[lane]    = __float2half_rn((x0-mean)*rs*g[lane]    + be[lane]);
    o[lane+32] = __float2half_rn((x1-mean)*rs*g[lane+32] + be[lane+32]);
}

// ---------------- k_qkv: HMMA GEMM, grid (256,3): y=0 Q, y=1 K, y=2 Vo -------
__global__ __launch_bounds__(256) void k_qkv(){
    __shared__ __half sA[64*72];    // pitch 144 B
    __shared__ __half sB[256*72];
    int t = threadIdx.x, lane = t & 31, wid = t >> 5;
    int t4 = lane & 3, gq = lane >> 2;
    int wq = wid & 1, wd = wid >> 1;
    int m0 = blockIdx.x*64;
    int ny = blockIdx.y;
    uint32_t sa = smem_u32(sA), sbb = smem_u32(sB);
    for (int i = t; i < 512; i += 256){
        int r = i >> 3, c = i & 7;
        *(uint4*)((char*)sA + r*144 + c*16) =
            *(const uint4*)((const char*)(g_xh + ((size_t)(m0+r))*64) + c*16);
    }
    for (int i = t; i < 2048; i += 256){
        int r = i >> 3, c = i & 7;
        *(uint4*)((char*)sB + r*144 + c*16) =
            *(const uint4*)((const char*)(g_Wh + (size_t)(ny*256 + r)*64) + c*16);
    }
    __syncthreads();
    uint32_t lo16 = lane & 15, hi16 = lane >> 4;
    uint32_t aQb = sa + (uint32_t)(wq*32 + lo16)*144 + hi16*16;
    uint32_t kl  = (uint32_t)((lane & 7) + ((lane >> 4) << 3));
    uint32_t bWb = sbb + (uint32_t)(wd*64)*144 + kl*144 + (uint32_t)((lane >> 3) & 1)*16;

    float out[2][8][4] = {};
    #pragma unroll
    for (int ks = 0; ks < 4; ks++){
        uint32_t hk = (uint32_t)ks*32;
        uint32_t aq[2][4];
        ldm_x4(aq[0], aQb + hk);
        ldm_x4(aq[1], aQb + 16u*144 + hk);
        #pragma unroll
        for (int ng = 0; ng < 4; ng++){
            uint32_t kf[4];
            ldm_x4(kf, bWb + (uint32_t)(ng*16)*144 + hk);
            #pragma unroll
            for (int mb = 0; mb < 2; mb++){
                mma16816(out[mb][ng*2],   aq[mb], kf);
                mma16816(out[mb][ng*2+1], aq[mb], kf+2);
            }
        }
    }
    const float* bp = g_bp + ny*256;
    if (ny < 2){
        __half* dst = (ny == 0) ? g_q : g_k;
        #pragma unroll
        for (int mb = 0; mb < 2; mb++){
            size_t rA = (size_t)m0 + (size_t)(wq*32 + mb*16 + gq);
            size_t rB = rA + 8;
            #pragma unroll
            for (int nt = 0; nt < 8; nt++){
                int col = wd*64 + nt*8 + 2*t4;
                float b0 = bp[col], b1 = bp[col+1];
                __half2 hA = __floats2half2_rn(out[mb][nt][0] + b0, out[mb][nt][1] + b1);
                __half2 hB = __floats2half2_rn(out[mb][nt][2] + b0, out[mb][nt][3] + b1);
                *(__half2*)&dst[rA*256 + col] = hA;
                *(__half2*)&dst[rB*256 + col] = hB;
            }
        }
    } else if (wd == 0){
        #pragma unroll
        for (int mb = 0; mb < 2; mb++){
            size_t rA = (size_t)m0 + (size_t)(wq*32 + mb*16 + gq);
            size_t rB = rA + 8;
            #pragma unroll
            for (int nt = 0; nt < 8; nt++){
                int col = nt*8 + 2*t4;
                float b0 = bp[col], b1 = bp[col+1];
                __half2 hA = __floats2half2_rn(out[mb][nt][0] + b0, out[mb][nt][1] + b1);
                __half2 hB = __floats2half2_rn(out[mb][nt][2] + b0, out[mb][nt][3] + b1);
                *(__half2*)&g_vo[rA*64 + col] = hA;
                *(__half2*)&g_vo[rB*64 + col] = hB;
            }
        }
    }
}

// ---------------- k_score: 64-query CTAs, warp = 32r x 64k x 1h --------------
// 256 threads = 8 warps: wq = wid&1 (32-row), wh = wid>>1 (head 0..3)
// Q fragments cached in registers across all 32 key tiles.
#define SC_SQO 0
#define SC_SK0 33792
#define SC_SK1 67584
#define SC_SW0 101376
#define SC_SW1 101632
#define SC_SLO 101888
#define SC_SLW 102912
#define SC_SMEM 103936

__global__ void __launch_bounds__(256,2) k_score(const float* __restrict__ gw){
    extern __shared__ char sm[];
    uint32_t sb = smem_u32(sm);
    int t = threadIdx.x, lane = t & 31, wid = t >> 5;
    int t4 = lane & 3, gq = lane >> 2;
    int wq = wid & 1, wh = wid >> 1;
    int b = blockIdx.x >> 5, qt = blockIdx.x & 31;
    size_t qrow0 = (size_t)b*NN + (size_t)qt*64;
    int RB0 = (int)(qrow0 >> 4);
    const char*  qg  = (const char*)(g_q + qrow0*256);
    const char*  kgb = (const char*)(g_k + (size_t)b*NN*256);
    const float* wb  = gw + (size_t)b*NN;
    float* sL = (float*)(sm + SC_SLO);
    float* sLW = (float*)(sm + SC_SLW);

    // prefetch K tile 0 + w tile 0
    for (int i = t; i < 2048; i += 256){
        int r = i >> 5, c = i & 31;
        cpa16(sb + SC_SK0 + r*528 + c*16, kgb + (size_t)r*512 + c*16);
    }
    if (t < 64) cpa4(sb + SC_SW0 + t*4, wb + t);
    CPA_COMMIT();
    // Q tile resident (64 x 512B, pitch 528)
    for (int i = t; i < 2048; i += 256){
        int r = i >> 5, c = i & 31;
        *(uint4*)(sm + SC_SQO + r*528 + c*16) = *(const uint4*)(qg + r*512 + c*16);
    }
    __syncthreads();

    // cache Q fragments for this warp's head: [mb][ks][4] = 32 regs
    uint32_t lo16 = lane & 15, hi16 = lane >> 4;
    uint32_t aQb = sb + SC_SQO + (uint32_t)(wq*32 + lo16)*528 + hi16*16;
    uint32_t aqc[2][4][4];
    #pragma unroll
    for (int mb = 0; mb < 2; mb++)
        #pragma unroll
        for (int ks = 0; ks < 4; ks++)
            ldm_x4(aqc[mb][ks], aQb + (uint32_t)(mb*16)*528 + (uint32_t)(wh*64 + ks*16)*2);

    uint32_t kl = (uint32_t)((lane & 7) + ((lane >> 4) << 3));
    float lacc[2][2], lwac[2][2];   // [mb][hf]
    #pragma unroll
    for (int mb = 0; mb < 2; mb++)
        #pragma unroll
        for (int hf = 0; hf < 2; hf++){ lacc[mb][hf] = 0.f; lwac[mb][hf] = 0.f; }

    for (int jt = 0; jt < 32; jt++){
        uint32_t koff = (jt & 1) ? SC_SK1 : SC_SK0;
        uint32_t woff = (jt & 1) ? SC_SW1 : SC_SW0;
        if (jt < 31){
            uint32_t kn = (jt & 1) ? SC_SK0 : SC_SK1;
            uint32_t wn = (jt & 1) ? SC_SW0 : SC_SW1;
            const char* src = kgb + (size_t)(jt+1)*32768;
            for (int i = t; i < 2048; i += 256){
                int r = i >> 5, c = i & 31;
                cpa16(sb + kn + r*528 + c*16, src + (size_t)r*512 + c*16);
            }
            if (t < 64) cpa4(sb + wn + t*4, wb + (jt+1)*64 + t);
            CPA_COMMIT();
            CPA_WAIT(1);
        } else {
            CPA_WAIT(0);
        }
        __syncthreads();
        const float* sw = (const float*)(sm + woff);
        uint32_t bKb = sb + koff + kl*528 + (uint32_t)((lane >> 3) & 1)*16;
        // process 4 blocks of 16 keys
        #pragma unroll
        for (int kb = 0; kb < 4; kb++){
            float sacc[2][2][4];
            #pragma unroll
            for (int mb = 0; mb < 2; mb++)
                #pragma unroll
                for (int nt = 0; nt < 2; nt++)
                    #pragma unroll
                    for (int q = 0; q < 4; q++) sacc[mb][nt][q] = 0.f;
            #pragma unroll
            for (int ks = 0; ks < 4; ks++){
                uint32_t kf[4];
                ldm_x4(kf, bKb + (uint32_t)(kb*16)*528 + (uint32_t)(wh*64 + ks*16)*2);
                #pragma unroll
                for (int mb = 0; mb < 2; mb++){
                    mma16816(sacc[mb][0], aqc[mb][ks], kf);
                    mma16816(sacc[mb][1], aqc[mb][ks], kf+2);
                }
            }
            // w + mask for this 16-key block
            float wv[4], mv[4];
            #pragma unroll
            for (int nt = 0; nt < 2; nt++){
                int kloc = kb*16 + nt*8 + 2*t4;
                wv[2*nt]   = sw[kloc];
                wv[2*nt+1] = sw[kloc+1];
                mv[2*nt]   = (wv[2*nt]   != 0.f) ? 1.f : 0.f;
                mv[2*nt+1] = (wv[2*nt+1] != 0.f) ? 1.f : 0.f;
            }
            #pragma unroll
            for (int mb = 0; mb < 2; mb++){
                size_t RB = (size_t)(RB0 + wq*2 + mb);
                uint32_t pk[4];
                #pragma unroll
                for (int nt = 0; nt < 2; nt++){
                    float e0 = ex2f(sacc[mb][nt][0]*CEXP);
                    float e1 = ex2f(sacc[mb][nt][1]*CEXP);
                    float e2 = ex2f(sacc[mb][nt][2]*CEXP);
                    float e3 = ex2f(sacc[mb][nt][3]*CEXP);
                    lacc[mb][0] = fmaf(e0, mv[2*nt], fmaf(e1, mv[2*nt+1], lacc[mb][0]));
                    lacc[mb][1] = fmaf(e2, mv[2*nt], fmaf(e3, mv[2*nt+1], lacc[mb][1]));
                    float ew0 = e0*wv[2*nt], ew1 = e1*wv[2*nt+1];
                    float ew2 = e2*wv[2*nt], ew3 = e3*wv[2*nt+1];
                    lwac[mb][0] += ew0 + ew1;
                    lwac[mb][1] += ew2 + ew3;
                    pk[nt*2]   = packbf2(ew0, ew1);
                    pk[nt*2+1] = packbf2(ew2, ew3);
                }
                int kbg = jt*4 + kb;
                g_e[(((RB*128 + (size_t)kbg)*4 + (size_t)wh) << 5) + lane] =
                    make_uint4(pk[0], pk[1], pk[2], pk[3]);
            }
        }
        __syncthreads();
    }
    // quad-reduce l, lw; single writer per (row, head)
    #pragma unroll
    for (int mb = 0; mb < 2; mb++)
        #pragma unroll
        for (int hf = 0; hf < 2; hf++){
            float v = lacc[mb][hf];
            v += __shfl_xor_sync(0xffffffffu, v, 1);
            v += __shfl_xor_sync(0xffffffffu, v, 2);
            float u = lwac[mb][hf];
            u += __shfl_xor_sync(0xffffffffu, u, 1);
            u += __shfl_xor_sync(0xffffffffu, u, 2);
            if (t4 == 0){
                int row = wq*32 + mb*16 + hf*8 + gq;
                sL[row*4 + wh] = v;
                sLW[row*4 + wh] = u;
            }
        }
    __syncthreads();
    if (wid < 2 && t4 == 0){   // wh == 0 warps, wq = wid
        #pragma unroll
        for (int mb = 0; mb < 2; mb++)
            #pragma unroll
            for (int hf = 0; hf < 2; hf++){
                int row = wq*32 + mb*16 + hf*8 + gq;
                float il[4], z = 0.f;
                #pragma unroll
                for (int h = 0; h < 4; h++){
                    il[h] = 1.f / sL[row*4+h];
                    z += sLW[row*4+h] * il[h];
                }
                g_il[qrow0 + row] = make_float4(il[0], il[1], il[2], il[3]);
                g_z[qrow0 + row] = 1.f / z;
            }
    }
}

// ---------------- k_av: out = (C @ Vo)/z, 64-wide; warp = 32r x 16k ----------
#define AV_SV0 0
#define AV_SV1 9216
#define AV_SPO 18432
#define AV_SIL 26624
#define AV_SRD 27648
#define AV_SMEM 93184

__device__ __forceinline__ uint32_t mixfrag(uint32_t e0, uint32_t e1, uint32_t e2, uint32_t e3,
                                            float i0, float i1, float i2, float i3){
    float lo = i0*bflo(e0) + i1*bflo(e1) + i2*bflo(e2) + i3*bflo(e3);
    float hi = i0*bfhi(e0) + i1*bfhi(e1) + i2*bfhi(e2) + i3*bfhi(e3);
    __half2 p = __floats2half2_rn(lo, hi);
    return *(uint32_t*)&p;
}

__global__ void __launch_bounds__(256,2) k_av(){
    extern __shared__ char sm[];
    uint32_t sb = smem_u32(sm);
    int t = threadIdx.x, lane = t & 31, wid = t >> 5;
    int t4 = lane & 3, gq = lane >> 2;
    int wq = wid & 1, kk = wid >> 1;
    size_t row0 = (size_t)blockIdx.x*64;
    int b = blockIdx.x >> 5;
    int RB0 = (int)(row0 >> 4);
    const char* vgb = (const char*)(g_vo + (size_t)b*NN*64);
    float4* silv = (float4*)(sm + AV_SIL);

    for (int i = t; i < 512; i += 256){
        int r = i >> 3, c = i & 7;
        cpa16(sb + AV_SV0 + r*144 + c*16, vgb + (size_t)r*128 + c*16);
    }
    CPA_COMMIT();

    uint32_t lo16 = lane & 15, hi16 = lane >> 4;
    if (t < 64) silv[t] = g_il[row0 + (size_t)t];

    float out[2][8][4];
    #pragma unroll
    for (int mb = 0; mb < 2; mb++)
        #pragma unroll
        for (int nt = 0; nt < 8; nt++)
            #pragma unroll
            for (int q = 0; q < 4; q++) out[mb][nt][q] = 0.f;

    for (int jt = 0; jt < 32; jt++){
        uint32_t voff = (jt & 1) ? AV_SV1 : AV_SV0;
        if (jt < 31){
            uint32_t vn = (jt & 1) ? AV_SV0 : AV_SV1;
            const char* src = vgb + (size_t)(jt+1)*8192;
            for (int i = t; i < 512; i += 256){
                int r = i >> 3, c = i & 7;
                cpa16(sb + vn + r*144 + c*16, src + (size_t)r*128 + c*16);
            }
            CPA_COMMIT();
            CPA_WAIT(1);
        } else {
            CPA_WAIT(0);
        }
        __syncthreads();
        #pragma unroll
        for (int uu = 0; uu < 2; uu++){
            int u = wid + uu*8;
            int RBl = u >> 2, kbl = u & 3;
            const uint4* ep = &g_e[((((size_t)(RB0 + RBl)*128 + (size_t)(jt*4 + kbl))*4) << 5) + lane];
            uint4 u0 = ep[0], u1 = ep[32], u2 = ep[64], u3 = ep[96];
            float4 a = silv[RBl*16 + gq];
            float4 c = silv[RBl*16 + 8 + gq];
            uint4 o;
            o.x = mixfrag(u0.x, u1.x, u2.x, u3.x, a.x, a.y, a.z, a.w);
            o.y = mixfrag(u0.y, u1.y, u2.y, u3.y, c.x, c.y, c.z, c.w);
            o.z = mixfrag(u0.z, u1.z, u2.z, u3.z, a.x, a.y, a.z, a.w);
            o.w = mixfrag(u0.w, u1.w, u2.w, u3.w, c.x, c.y, c.z, c.w);
            *(uint4*)(sm + AV_SPO + (u*32 + lane)*16) = o;
        }
        __syncthreads();
        uint32_t aF[2][4];
        #pragma unroll
        for (int mb = 0; mb < 2; mb++){
            uint4 v4 = *(const uint4*)(sm + AV_SPO + ((((wq*2 + mb)*4 + kk)*32 + lane))*16);
            aF[mb][0] = v4.x; aF[mb][1] = v4.y; aF[mb][2] = v4.z; aF[mb][3] = v4.w;
        }
        uint32_t bVb = sb + voff + (uint32_t)(kk*16 + lo16)*144 + hi16*16;
        #pragma unroll
        for (int dt2 = 0; dt2 < 4; dt2++){
            uint32_t vf[4];
            ldm_x4t(vf, bVb + (uint32_t)dt2*32);
            mma16816(out[0][dt2*2],   aF[0], vf);
            mma16816(out[0][dt2*2+1], aF[0], vf+2);
            mma16816(out[1][dt2*2],   aF[1], vf);
            mma16816(out[1][dt2*2+1], aF[1], vf+2);
        }
        __syncthreads();
    }
    float* srd = (float*)(sm + AV_SRD);
    #pragma unroll
    for (int mb = 0; mb < 2; mb++){
        int rA = wq*32 + mb*16 + gq;
        int rB = rA + 8;
        #pragma unroll
        for (int nt = 0; nt < 8; nt++){
            int col = nt*8 + 2*t4;
            *(float2*)&srd[(kk*64 + rA)*64 + col] = make_float2(out[mb][nt][0], out[mb][nt][1]);
            *(float2*)&srd[(kk*64 + rB)*64 + col] = make_float2(out[mb][nt][2], out[mb][nt][3]);
        }
    }
    __syncthreads();
    for (int i = t; i < 1024; i += 256){
        int row = i >> 4, c4 = (i & 15)*4;
        float4 s0 = *(const float4*)&srd[(row)*64 + c4];
        float4 s1 = *(const float4*)&srd[(64 + row)*64 + c4];
        float4 s2 = *(const float4*)&srd[(128 + row)*64 + c4];
        float4 s3 = *(const float4*)&srd[(192 + row)*64 + c4];
        float iz = g_z[row0 + row];
        float4 o = make_float4((s0.x+s1.x+s2.x+s3.x)*iz, (s0.y+s1.y+s2.y+s3.y)*iz,
                               (s0.z+s1.z+s2.z+s3.z)*iz, (s0.w+s1.w+s2.w+s3.w)*iz);
        *(float4*)&g_av[(row0 + row)*64 + c4] = o;
    }
}

// ---------------- k_tail ----------------
__global__ __launch_bounds__(256) void k_tail(const float* __restrict__ ob,
                                              const float* __restrict__ x,
                                              const float* __restrict__ g,
                                              const float* __restrict__ be,
                                              const float* __restrict__ fw,
                                              const float* __restrict__ fb,
                                              float* __restrict__ out){
    __shared__ float sA[64*68];
    __shared__ float sB[64*68];
    __shared__ float sy[8][64];
    int m0 = blockIdx.x*64;
    int t = threadIdx.x, lane = t & 31, w = t >> 5;
    for (int i = t; i < 1024; i += 256){
        int r = i >> 4, c = i & 15;
        float4 xv = *(const float4*)&x[((size_t)(m0+r))*64 + c*4];
        float4 av = *(const float4*)&g_av[((size_t)(m0+r))*64 + c*4];
        float4 obv = *(const float4*)&ob[c*4];
        sA[r*68 + c*4 + 0] = xv.x + av.x + obv.x;
        sA[r*68 + c*4 + 1] = xv.y + av.y + obv.y;
        sA[r*68 + c*4 + 2] = xv.z + av.z + obv.z;
        sA[r*68 + c*4 + 3] = xv.w + av.w + obv.w;
    }
    for (int i = t; i < 4096; i += 256) sB[(i>>6)*65 + (i&63)] = fw[i];
    __syncthreads();
    #pragma unroll 1
    for (int rr = 0; rr < 8; rr++){
        int rl = w*8 + rr;
        float o0 = sA[rl*68 + lane], o1 = sA[rl*68 + lane + 32];
        float mean = wsum(o0+o1)*(1.f/64.f);
        float msq  = wsum(o0*o0+o1*o1)*(1.f/64.f);
        float rs = rsqrtf(msq - mean*mean + 1e-5f);
        sy[w][lane]    = (o0-mean)*rs*g[lane]    + be[lane];
        sy[w][lane+32] = (o1-mean)*rs*g[lane+32] + be[lane+32];
        __syncwarp();
        float a0 = fb[lane], a1 = fb[lane+32];
        #pragma unroll 8
        for (int c = 0; c < 64; c++){
            float yv = sy[w][c];
            a0 += yv * sB[lane*65 + c];
            a1 += yv * sB[(lane+32)*65 + c];
        }
        float s0 = o0 + softplusf(a0);
        float s1 = o1 + softplusf(a1);
        float m2 = wsum(s0+s1)*(1.f/64.f);
        float q2 = wsum(s0*s0+s1*s1)*(1.f/64.f);
        float r2 = rsqrtf(q2 - m2*m2 + 1e-5f);
        size_t m = m0 + rl;
        out[m*64 + lane]    = (s0-m2)*r2*g[lane]    + be[lane];
        out[m*64 + lane+32] = (s1-m2)*r2*g[lane+32] + be[lane+32];
        __syncwarp();
    }
}

// ---------------- launch ----------------
extern "C" void kernel_launch(void* const* d_in, const int* in_sizes, int n_in,
                              void* d_out, int out_size){
    (void)in_sizes; (void)n_in; (void)out_size;
    const float* x     = (const float*)d_in[0];
    const float* wts   = (const float*)d_in[1];
    const float* ln_g  = (const float*)d_in[2];
    const float* ln_b  = (const float*)d_in[3];
    const float* wq_w  = (const float*)d_in[4];
    const float* wq_b  = (const float*)d_in[5];
    const float* wk_w  = (const float*)d_in[6];
    const float* wk_b  = (const float*)d_in[7];
    const float* wv_w  = (const float*)d_in[8];
    const float* wv_b  = (const float*)d_in[9];
    const float* mq_w  = (const float*)d_in[10];
    const float* mq_b  = (const float*)d_in[11];
    const float* mk_w  = (const float*)d_in[12];
    const float* mk_b  = (const float*)d_in[13];
    const float* out_w = (const float*)d_in[14];
    const float* out_b = (const float*)d_in[15];
    const float* ffn_w = (const float*)d_in[16];
    const float* ffn_b = (const float*)d_in[17];
    float* out = (float*)d_out;

    cudaFuncSetAttribute(k_score, cudaFuncAttributeMaxDynamicSharedMemorySize, SC_SMEM);
    cudaFuncSetAttribute(k_av,    cudaFuncAttributeMaxDynamicSharedMemorySize, AV_SMEM);

    k_fold<<<768, 64>>>(wq_w, wq_b, wk_w, wk_b, wv_w, wv_b, mq_w, mq_b, mk_w, mk_b, out_w);
    k_ln<<<ROWS/8, 256>>>(x, ln_g, ln_b);
    k_qkv<<<dim3(ROWS/64, 3), 256>>>();
    k_score<<<256, 256, SC_SMEM>>>(wts);
    k_av<<<256, 256, AV_SMEM>>>();
    k_tail<<<ROWS/64, 256>>>(out_b, x, ln_g, ln_b, ffn_w, ffn_b, out);
}

// round 13
// speedup vs baseline: 1.1142x; 1.1142x over previous
#include <cuda_runtime.h>
#include <cuda_fp16.h>
#include <cuda_bf16.h>
#include <math.h>
#include <stdint.h>

#define BB 8
#define NN 2048
#define EE 64
#define DD 256
#define ROWS (BB*NN)   // 16384

// ---------------- scratch (static device globals; no allocs) ----------------
__device__ __align__(16) __half g_xh[ROWS*EE];            // LN(x) in fp16
__device__ __align__(16) __half g_q[ROWS*DD];
__device__ __align__(16) __half g_k[ROWS*DD];
__device__ __align__(16) __nv_bfloat16 g_vo[ROWS*EE];     // V @ ow^T (+ ow@wvb), bf16
__device__ float g_av[ROWS*EE];                            // attention output, 64-wide fp32
__device__ __align__(16) __half g_Wh[768*64];              // folded weights
__device__ float g_bp[768];

#define CEXP 0.18033688f   // 0.125 * log2(e)

// ---------------- generic helpers ----------------
__device__ __forceinline__ float wsum(float v){
    v += __shfl_xor_sync(0xffffffffu, v, 16);
    v += __shfl_xor_sync(0xffffffffu, v, 8);
    v += __shfl_xor_sync(0xffffffffu, v, 4);
    v += __shfl_xor_sync(0xffffffffu, v, 2);
    v += __shfl_xor_sync(0xffffffffu, v, 1);
    return v;
}
__device__ __forceinline__ float softplusf(float x){
    if (x > 20.f) return x;
    return log1pf(expf(x));
}
__device__ __forceinline__ uint32_t smem_u32(const void* p){
    uint32_t a;
    asm("{ .reg .u64 t; cvta.to.shared.u64 t, %1; cvt.u32.u64 %0, t; }" : "=r"(a) : "l"(p));
    return a;
}
__device__ __forceinline__ float ex2f(float x){
    float r;
    asm("ex2.approx.f32 %0, %1;" : "=f"(r) : "f"(x));
    return r;
}
__device__ __forceinline__ uint32_t packbf2(float a, float b){
    __nv_bfloat162 h = __floats2bfloat162_rn(a, b);
    return *(uint32_t*)&h;
}

// ---------------- cp.async helpers (sm_80+ baseline) ----------------
__device__ __forceinline__ void cpa16(uint32_t dst, const void* src){
    asm volatile("cp.async.cg.shared.global [%0], [%1], 16;" :: "r"(dst), "l"(src) : "memory");
}
__device__ __forceinline__ void cpa4(uint32_t dst, const void* src){
    asm volatile("cp.async.ca.shared.global [%0], [%1], 4;" :: "r"(dst), "l"(src) : "memory");
}
#define CPA_COMMIT() asm volatile("cp.async.commit_group;" ::: "memory")
#define CPA_WAIT(n)  asm volatile("cp.async.wait_group %0;" :: "n"(n) : "memory")

// ---------------- mma.sync / ldmatrix helpers (baseline PTX, sm_80+) --------
__device__ __forceinline__ void ldm_x4(uint32_t a[4], uint32_t addr){
    asm volatile("ldmatrix.sync.aligned.m8n8.x4.shared.b16 {%0,%1,%2,%3}, [%4];"
        : "=r"(a[0]), "=r"(a[1]), "=r"(a[2]), "=r"(a[3]) : "r"(addr));
}
__device__ __forceinline__ void ldm_x4t(uint32_t a[4], uint32_t addr){
    asm volatile("ldmatrix.sync.aligned.m8n8.x4.trans.shared.b16 {%0,%1,%2,%3}, [%4];"
        : "=r"(a[0]), "=r"(a[1]), "=r"(a[2]), "=r"(a[3]) : "r"(addr));
}
__device__ __forceinline__ void mma16816(float c[4], const uint32_t a[4], const uint32_t b[2]){
    asm volatile("mma.sync.aligned.m16n8k16.row.col.f32.f16.f16.f32 "
        "{%0,%1,%2,%3}, {%4,%5,%6,%7}, {%8,%9}, {%0,%1,%2,%3};"
        : "+f"(c[0]), "+f"(c[1]), "+f"(c[2]), "+f"(c[3])
        : "r"(a[0]), "r"(a[1]), "r"(a[2]), "r"(a[3]), "r"(b[0]), "r"(b[1]));
}
__device__ __forceinline__ void mma16816bf(float c[4], const uint32_t a[4], const uint32_t b[2]){
    asm volatile("mma.sync.aligned.m16n8k16.row.col.f32.bf16.bf16.f32 "
        "{%0,%1,%2,%3}, {%4,%5,%6,%7}, {%8,%9}, {%0,%1,%2,%3};"
        : "+f"(c[0]), "+f"(c[1]), "+f"(c[2]), "+f"(c[3])
        : "r"(a[0]), "r"(a[1]), "r"(a[2]), "r"(a[3]), "r"(b[0]), "r"(b[1]));
}

// ---------------- fold: q/k effective weights + Wvo = ow @ wv ---------------
__global__ void k_fold(const float* __restrict__ wq_w, const float* __restrict__ wq_b,
                       const float* __restrict__ wk_w, const float* __restrict__ wk_b,
                       const float* __restrict__ wv_w, const float* __restrict__ wv_b,
                       const float* __restrict__ mq_w, const float* __restrict__ mq_b,
                       const float* __restrict__ mk_w, const float* __restrict__ mk_b,
                       const float* __restrict__ ow){
    int r = blockIdx.x, e = threadIdx.x;
    if (r < 256){
        float acc = 0.f;
        for (int c = 0; c < 256; c++) acc += mq_w[r*256+c]*wq_w[c*64+e];
        g_Wh[r*64+e] = __float2half_rn(acc);
        if (e == 0){
            float bb = mq_b[r];
            for (int c = 0; c < 256; c++) bb += mq_w[r*256+c]*wq_b[c];
            g_bp[r] = bb;
        }
    } else if (r < 512){
        int rr = r - 256;
        float acc = 0.f;
        for (int c = 0; c < 256; c++) acc += mk_w[rr*256+c]*wk_w[c*64+e];
        g_Wh[r*64+e] = __float2half_rn(acc);
        if (e == 0){
            float bb = mk_b[rr];
            for (int c = 0; c < 256; c++) bb += mk_w[rr*256+c]*wk_b[c];
            g_bp[r] = bb;
        }
    } else if (r < 576){
        int rr = r - 512;
        float acc = 0.f;
        for (int d = 0; d < 256; d++) acc += ow[rr*256+d]*wv_w[d*64+e];
        g_Wh[r*64+e] = __float2half_rn(acc);
        if (e == 0){
            float bb = 0.f;
            for (int d = 0; d < 256; d++) bb += ow[rr*256+d]*wv_b[d];
            g_bp[r] = bb;
        }
    } else {
        g_Wh[r*64+e] = __float2half_rn(0.f);
        if (e == 0) g_bp[r] = 0.f;
    }
}

// ---------------- LayerNorm over E=64 -> fp16: one warp per row --------------
__global__ __launch_bounds__(256) void k_ln(const float* __restrict__ x,
                                            const float* __restrict__ g,
                                            const float* __restrict__ be){
    int t = threadIdx.x, lane = t & 31, w = t >> 5;
    size_t row = (size_t)blockIdx.x*8 + w;
    const float* xr = x + row*64;
    float x0 = xr[lane], x1 = xr[lane+32];
    float mean = wsum(x0+x1)*(1.f/64.f);
    float msq  = wsum(x0*x0+x1*x1)*(1.f/64.f);
    float rs = rsqrtf(msq - mean*mean + 1e-5f);
    __half* o = g_xh + row*64;
    o[lane]    = __float2half_rn((x0-mean)*rs*g[lane]    + be[lane]);
    o[lane+32] = __float2half_rn((x1-mean)*rs*g[lane+32] + be[lane+32]);
}

// ---------------- k_qkv: HMMA GEMM, grid (256,3): y=0 Q, y=1 K, y=2 Vo -------
__global__ __launch_bounds__(256) void k_qkv(){
    __shared__ __half sA[64*72];    // pitch 144 B
    __shared__ __half sB[256*72];
    int t = threadIdx.x, lane = t & 31, wid = t >> 5;
    int t4 = lane & 3, gq = lane >> 2;
    int wq = wid & 1, wd = wid >> 1;
    int m0 = blockIdx.x*64;
    int ny = blockIdx.y;
    uint32_t sa = smem_u32(sA), sbb = smem_u32(sB);
    for (int i = t; i < 512; i += 256){
        int r = i >> 3, c = i & 7;
        *(uint4*)((char*)sA + r*144 + c*16) =
            *(const uint4*)((const char*)(g_xh + ((size_t)(m0+r))*64) + c*16);
    }
    for (int i = t; i < 2048; i += 256){
        int r = i >> 3, c = i & 7;
        *(uint4*)((char*)sB + r*144 + c*16) =
            *(const uint4*)((const char*)(g_Wh + (size_t)(ny*256 + r)*64) + c*16);
    }
    __syncthreads();
    uint32_t lo16 = lane & 15, hi16 = lane >> 4;
    uint32_t aQb = sa + (uint32_t)(wq*32 + lo16)*144 + hi16*16;
    uint32_t kl  = (uint32_t)((lane & 7) + ((lane >> 4) << 3));
    uint32_t bWb = sbb + (uint32_t)(wd*64)*144 + kl*144 + (uint32_t)((lane >> 3) & 1)*16;

    float out[2][8][4] = {};
    #pragma unroll
    for (int ks = 0; ks < 4; ks++){
        uint32_t hk = (uint32_t)ks*32;
        uint32_t aq[2][4];
        ldm_x4(aq[0], aQb + hk);
        ldm_x4(aq[1], aQb + 16u*144 + hk);
        #pragma unroll
        for (int ng = 0; ng < 4; ng++){
            uint32_t kf[4];
            ldm_x4(kf, bWb + (uint32_t)(ng*16)*144 + hk);
            #pragma unroll
            for (int mb = 0; mb < 2; mb++){
                mma16816(out[mb][ng*2],   aq[mb], kf);
                mma16816(out[mb][ng*2+1], aq[mb], kf+2);
            }
        }
    }
    const float* bp = g_bp + ny*256;
    if (ny < 2){
        __half* dst = (ny == 0) ? g_q : g_k;
        #pragma unroll
        for (int mb = 0; mb < 2; mb++){
            size_t rA = (size_t)m0 + (size_t)(wq*32 + mb*16 + gq);
            size_t rB = rA + 8;
            #pragma unroll
            for (int nt = 0; nt < 8; nt++){
                int col = wd*64 + nt*8 + 2*t4;
                float b0 = bp[col], b1 = bp[col+1];
                __half2 hA = __floats2half2_rn(out[mb][nt][0] + b0, out[mb][nt][1] + b1);
                __half2 hB = __floats2half2_rn(out[mb][nt][2] + b0, out[mb][nt][3] + b1);
                *(__half2*)&dst[rA*256 + col] = hA;
                *(__half2*)&dst[rB*256 + col] = hB;
            }
        }
    } else if (wd == 0){
        #pragma unroll
        for (int mb = 0; mb < 2; mb++){
            size_t rA = (size_t)m0 + (size_t)(wq*32 + mb*16 + gq);
            size_t rB = rA + 8;
            #pragma unroll
            for (int nt = 0; nt < 8; nt++){
                int col = nt*8 + 2*t4;
                float b0 = bp[col], b1 = bp[col+1];
                uint32_t pA = packbf2(out[mb][nt][0] + b0, out[mb][nt][1] + b1);
                uint32_t pB = packbf2(out[mb][nt][2] + b0, out[mb][nt][3] + b1);
                *(uint32_t*)&g_vo[rA*64 + col] = pA;
                *(uint32_t*)&g_vo[rB*64 + col] = pB;
            }
        }
    }
}

// ---------------- k_attn: fused score+softmax+AV, no NxN / P materialization -
// 256 threads = 8 warps: wq = wid&1 (32-row group), wh = wid>>1 (head 0..3)
// 32-key tiles; per-head partial S accumulated in registers via bf16 MMA;
// epilogue: cross-head reduction through smem overlay, divide by z.
#define AT_SQO 0
#define AT_SK0 33792
#define AT_SK1 50688
#define AT_SV0 67584
#define AT_SV1 72192
#define AT_SW0 76800
#define AT_SW1 76928
#define AT_SLO 77056
#define AT_SLW 78080
#define AT_SMEM 79104
// epilogue reduction buffer: 4 planes x 64 rows x 64 cols fp32 = 64KB, overlays [0, 65536)

__global__ void __launch_bounds__(256,2) k_attn(const float* __restrict__ gw){
    extern __shared__ char sm[];
    uint32_t sb = smem_u32(sm);
    int t = threadIdx.x, lane = t & 31, wid = t >> 5;
    int t4 = lane & 3, gq = lane >> 2;
    int wq = wid & 1, wh = wid >> 1;
    int b = blockIdx.x >> 5, qt = blockIdx.x & 31;
    size_t qrow0 = (size_t)b*NN + (size_t)qt*64;
    const char*  qg  = (const char*)(g_q + qrow0*256);
    const char*  kgb = (const char*)(g_k + (size_t)b*NN*256);
    const char*  vgb = (const char*)(g_vo + (size_t)b*NN*64);
    const float* wb  = gw + (size_t)b*NN;
    float* sL = (float*)(sm + AT_SLO);
    float* sLW = (float*)(sm + AT_SLW);

    // prefetch K tile 0 (32 keys x 512B), Vo tile 0 (32 x 128B), w tile 0
    for (int i = t; i < 1024; i += 256){
        int r = i >> 5, c = i & 31;
        cpa16(sb + AT_SK0 + r*528 + c*16, kgb + (size_t)r*512 + c*16);
    }
    {
        int r = t >> 3, c = t & 7;
        cpa16(sb + AT_SV0 + r*144 + c*16, vgb + (size_t)r*128 + c*16);
    }
    if (t < 32) cpa4(sb + AT_SW0 + t*4, wb + t);
    CPA_COMMIT();
    // Q tile resident (64 x 512B, pitch 528)
    for (int i = t; i < 2048; i += 256){
        int r = i >> 5, c = i & 31;
        *(uint4*)(sm + AT_SQO + r*528 + c*16) = *(const uint4*)(qg + r*512 + c*16);
    }

    uint32_t lo16 = lane & 15, hi16 = lane >> 4;
    uint32_t aQb = sb + AT_SQO + (uint32_t)(wq*32 + lo16)*528 + hi16*16;
    uint32_t kl  = (uint32_t)((lane & 7) + ((lane >> 4) << 3));

    float out[2][8][4];
    #pragma unroll
    for (int mb = 0; mb < 2; mb++)
        #pragma unroll
        for (int nt = 0; nt < 8; nt++)
            #pragma unroll
            for (int q = 0; q < 4; q++) out[mb][nt][q] = 0.f;
    float lacc[2][2], lwac[2][2];
    #pragma unroll
    for (int mb = 0; mb < 2; mb++)
        #pragma unroll
        for (int hf = 0; hf < 2; hf++){ lacc[mb][hf] = 0.f; lwac[mb][hf] = 0.f; }

    for (int jt = 0; jt < 64; jt++){
        uint32_t koff = (jt & 1) ? AT_SK1 : AT_SK0;
        uint32_t voff = (jt & 1) ? AT_SV1 : AT_SV0;
        uint32_t woff = (jt & 1) ? AT_SW1 : AT_SW0;
        if (jt < 63){
            uint32_t kn = (jt & 1) ? AT_SK0 : AT_SK1;
            uint32_t vn = (jt & 1) ? AT_SV0 : AT_SV1;
            uint32_t wn = (jt & 1) ? AT_SW0 : AT_SW1;
            const char* ksrc = kgb + (size_t)(jt+1)*16384;
            const char* vsrc = vgb + (size_t)(jt+1)*4096;
            for (int i = t; i < 1024; i += 256){
                int r = i >> 5, c = i & 31;
                cpa16(sb + kn + r*528 + c*16, ksrc + (size_t)r*512 + c*16);
            }
            {
                int r = t >> 3, c = t & 7;
                cpa16(sb + vn + r*144 + c*16, vsrc + (size_t)r*128 + c*16);
            }
            if (t < 32) cpa4(sb + wn + t*4, wb + (jt+1)*32 + t);
            CPA_COMMIT();
            CPA_WAIT(1);
        } else {
            CPA_WAIT(0);
        }
        __syncthreads();
        const float* sw = (const float*)(sm + woff);
        uint32_t bK = sb + koff + kl*528 + (uint32_t)((lane >> 3) & 1)*16;
        uint32_t bV = sb + voff + lo16*144 + hi16*16;
        #pragma unroll
        for (int kb = 0; kb < 2; kb++){
            float sacc[2][2][4];
            #pragma unroll
            for (int mb = 0; mb < 2; mb++)
                #pragma unroll
                for (int nt = 0; nt < 2; nt++)
                    #pragma unroll
                    for (int q = 0; q < 4; q++) sacc[mb][nt][q] = 0.f;
            #pragma unroll
            for (int ks = 0; ks < 4; ks++){
                uint32_t hk = (uint32_t)(wh*64 + ks*16)*2;
                uint32_t aq[2][4];
                ldm_x4(aq[0], aQb + hk);
                ldm_x4(aq[1], aQb + 16u*528 + hk);
                uint32_t kf[4];
                ldm_x4(kf, bK + (uint32_t)(kb*16)*528 + hk);
                #pragma unroll
                for (int mb = 0; mb < 2; mb++){
                    mma16816(sacc[mb][0], aq[mb], kf);
                    mma16816(sacc[mb][1], aq[mb], kf+2);
                }
            }
            float wv[4], mv[4];
            #pragma unroll
            for (int nt = 0; nt < 2; nt++){
                int kloc = kb*16 + nt*8 + 2*t4;
                wv[2*nt]   = sw[kloc];
                wv[2*nt+1] = sw[kloc+1];
                mv[2*nt]   = (wv[2*nt]   != 0.f) ? 1.f : 0.f;
                mv[2*nt+1] = (wv[2*nt+1] != 0.f) ? 1.f : 0.f;
            }
            uint32_t pk2[2][4];
            #pragma unroll
            for (int mb = 0; mb < 2; mb++){
                #pragma unroll
                for (int nt = 0; nt < 2; nt++){
                    float e0 = ex2f(sacc[mb][nt][0]*CEXP);
                    float e1 = ex2f(sacc[mb][nt][1]*CEXP);
                    float e2 = ex2f(sacc[mb][nt][2]*CEXP);
                    float e3 = ex2f(sacc[mb][nt][3]*CEXP);
                    lacc[mb][0] = fmaf(e0, mv[2*nt], fmaf(e1, mv[2*nt+1], lacc[mb][0]));
                    lacc[mb][1] = fmaf(e2, mv[2*nt], fmaf(e3, mv[2*nt+1], lacc[mb][1]));
                    float ew0 = e0*wv[2*nt], ew1 = e1*wv[2*nt+1];
                    float ew2 = e2*wv[2*nt], ew3 = e3*wv[2*nt+1];
                    lwac[mb][0] += ew0 + ew1;
                    lwac[mb][1] += ew2 + ew3;
                    pk2[mb][nt*2]   = packbf2(ew0, ew1);
                    pk2[mb][nt*2+1] = packbf2(ew2, ew3);
                }
            }
            // AV: S += ew[32rows x 16keys] @ Vo[16keys x 64cols]
            #pragma unroll
            for (int dt2 = 0; dt2 < 4; dt2++){
                uint32_t vf[4];
                ldm_x4t(vf, bV + (uint32_t)(kb*16)*144 + (uint32_t)dt2*32);
                mma16816bf(out[0][dt2*2],   pk2[0], vf);
                mma16816bf(out[0][dt2*2+1], pk2[0], vf+2);
                mma16816bf(out[1][dt2*2],   pk2[1], vf);
                mma16816bf(out[1][dt2*2+1], pk2[1], vf+2);
            }
        }
        __syncthreads();
    }
    // quad-reduce l, lw; single writer per (row, head)
    #pragma unroll
    for (int mb = 0; mb < 2; mb++)
        #pragma unroll
        for (int hf = 0; hf < 2; hf++){
            float v = lacc[mb][hf];
            v += __shfl_xor_sync(0xffffffffu, v, 1);
            v += __shfl_xor_sync(0xffffffffu, v, 2);
            float u = lwac[mb][hf];
            u += __shfl_xor_sync(0xffffffffu, u, 1);
            u += __shfl_xor_sync(0xffffffffu, u, 2);
            if (t4 == 0){
                int row = wq*32 + mb*16 + hf*8 + gq;
                sL[row*4 + wh] = v;
                sLW[row*4 + wh] = u;
            }
        }
    __syncthreads();
    // scale by il_h, dump per-head planes into reduction overlay [0,64KB)
    float* red = (float*)sm;
    #pragma unroll
    for (int mb = 0; mb < 2; mb++){
        int rA = wq*32 + mb*16 + gq;
        int rB = rA + 8;
        float ilA = 1.f / sL[rA*4 + wh];
        float ilB = 1.f / sL[rB*4 + wh];
        #pragma unroll
        for (int nt = 0; nt < 8; nt++){
            int col = nt*8 + 2*t4;
            *(float2*)&red[(wh*64 + rA)*64 + col] = make_float2(out[mb][nt][0]*ilA, out[mb][nt][1]*ilA);
            *(float2*)&red[(wh*64 + rB)*64 + col] = make_float2(out[mb][nt][2]*ilB, out[mb][nt][3]*ilB);
        }
    }
    __syncthreads();
    for (int i = t; i < 1024; i += 256){
        int row = i >> 4, c4 = (i & 15)*4;
        float4 s0 = *(const float4*)&red[(row)*64 + c4];
        float4 s1 = *(const float4*)&red[(64 + row)*64 + c4];
        float4 s2 = *(const float4*)&red[(128 + row)*64 + c4];
        float4 s3 = *(const float4*)&red[(192 + row)*64 + c4];
        float z = sLW[row*4+0]/sL[row*4+0] + sLW[row*4+1]/sL[row*4+1]
                + sLW[row*4+2]/sL[row*4+2] + sLW[row*4+3]/sL[row*4+3];
        float iz = 1.f / z;
        float4 o = make_float4((s0.x+s1.x+s2.x+s3.x)*iz, (s0.y+s1.y+s2.y+s3.y)*iz,
                               (s0.z+s1.z+s2.z+s3.z)*iz, (s0.w+s1.w+s2.w+s3.w)*iz);
        *(float4*)&g_av[(qrow0 + (size_t)row)*64 + c4] = o;
    }
}

// ---------------- k_tail: out1 = x + av + ob; out = LN(out1 + sp(LN(out1)@fw^T + fb))
__global__ __launch_bounds__(256) void k_tail(const float* __restrict__ ob,
                                              const float* __restrict__ x,
                                              const float* __restrict__ g,
                                              const float* __restrict__ be,
                                              const float* __restrict__ fw,
                                              const float* __restrict__ fb,
                                              float* __restrict__ out){
    __shared__ float sA[64*68];
    __shared__ float sB[64*68];
    __shared__ float sy[8][64];
    int m0 = blockIdx.x*64;
    int t = threadIdx.x, lane = t & 31, w = t >> 5;
    for (int i = t; i < 1024; i += 256){
        int r = i >> 4, c = i & 15;
        float4 xv = *(const float4*)&x[((size_t)(m0+r))*64 + c*4];
        float4 av = *(const float4*)&g_av[((size_t)(m0+r))*64 + c*4];
        float4 obv = *(const float4*)&ob[c*4];
        sA[r*68 + c*4 + 0] = xv.x + av.x + obv.x;
        sA[r*68 + c*4 + 1] = xv.y + av.y + obv.y;
        sA[r*68 + c*4 + 2] = xv.z + av.z + obv.z;
        sA[r*68 + c*4 + 3] = xv.w + av.w + obv.w;
    }
    for (int i = t; i < 4096; i += 256) sB[(i>>6)*65 + (i&63)] = fw[i];
    __syncthreads();
    #pragma unroll 1
    for (int rr = 0; rr < 8; rr++){
        int rl = w*8 + rr;
        float o0 = sA[rl*68 + lane], o1 = sA[rl*68 + lane + 32];
        float mean = wsum(o0+o1)*(1.f/64.f);
        float msq  = wsum(o0*o0+o1*o1)*(1.f/64.f);
        float rs = rsqrtf(msq - mean*mean + 1e-5f);
        sy[w][lane]    = (o0-mean)*rs*g[lane]    + be[lane];
        sy[w][lane+32] = (o1-mean)*rs*g[lane+32] + be[lane+32];
        __syncwarp();
        float a0 = fb[lane], a1 = fb[lane+32];
        #pragma unroll 8
        for (int c = 0; c < 64; c++){
            float yv = sy[w][c];
            a0 += yv * sB[lane*65 + c];
            a1 += yv * sB[(lane+32)*65 + c];
        }
        float s0 = o0 + softplusf(a0);
        float s1 = o1 + softplusf(a1);
        float m2 = wsum(s0+s1)*(1.f/64.f);
        float q2 = wsum(s0*s0+s1*s1)*(1.f/64.f);
        float r2 = rsqrtf(q2 - m2*m2 + 1e-5f);
        size_t m = m0 + rl;
        out[m*64 + lane]    = (s0-m2)*r2*g[lane]    + be[lane];
        out[m*64 + lane+32] = (s1-m2)*r2*g[lane+32] + be[lane+32];
        __syncwarp();
    }
}

// ---------------- launch ----------------
extern "C" void kernel_launch(void* const* d_in, const int* in_sizes, int n_in,
                              void* d_out, int out_size){
    (void)in_sizes; (void)n_in; (void)out_size;
    const float* x     = (const float*)d_in[0];
    const float* wts   = (const float*)d_in[1];
    const float* ln_g  = (const float*)d_in[2];
    const float* ln_b  = (const float*)d_in[3];
    const float* wq_w  = (const float*)d_in[4];
    const float* wq_b  = (const float*)d_in[5];
    const float* wk_w  = (const float*)d_in[6];
    const float* wk_b  = (const float*)d_in[7];
    const float* wv_w  = (const float*)d_in[8];
    const float* wv_b  = (const float*)d_in[9];
    const float* mq_w  = (const float*)d_in[10];
    const float* mq_b  = (const float*)d_in[11];
    const float* mk_w  = (const float*)d_in[12];
    const float* mk_b  = (const float*)d_in[13];
    const float* out_w = (const float*)d_in[14];
    const float* out_b = (const float*)d_in[15];
    const float* ffn_w = (const float*)d_in[16];
    const float* ffn_b = (const float*)d_in[17];
    float* out = (float*)d_out;

    cudaFuncSetAttribute(k_attn, cudaFuncAttributeMaxDynamicSharedMemorySize, AT_SMEM);

    k_fold<<<768, 64>>>(wq_w, wq_b, wk_w, wk_b, wv_w, wv_b, mq_w, mq_b, mk_w, mk_b, out_w);
    k_ln<<<ROWS/8, 256>>>(x, ln_g, ln_b);
    k_qkv<<<dim3(ROWS/64, 3), 256>>>();
    k_attn<<<256, 256, AT_SMEM>>>(wts);
    k_tail<<<ROWS/64, 256>>>(out_b, x, ln_g, ln_b, ffn_w, ffn_b, out);
}

// round 14
// speedup vs baseline: 1.2307x; 1.1045x over previous
#include <cuda_runtime.h>
#include <cuda_fp16.h>
#include <cuda_bf16.h>
#include <math.h>
#include <stdint.h>

#define BB 8
#define NN 2048
#define EE 64
#define DD 256
#define ROWS (BB*NN)   // 16384

// ---------------- scratch (static device globals; no allocs) ----------------
__device__ __align__(16) __half g_xh[ROWS*EE];            // LN(x) in fp16
__device__ __align__(16) __half g_q[ROWS*DD];
__device__ __align__(16) __half g_k[ROWS*DD];
__device__ __align__(16) __nv_bfloat16 g_vo[ROWS*EE];     // V @ ow^T (+ ow@wvb), bf16
__device__ float g_av[ROWS*EE];                            // attention output, 64-wide fp32
__device__ __align__(16) __half g_Wh[768*64];              // folded weights
__device__ float g_bp[768];

#define CEXP 0.18033688f   // 0.125 * log2(e)

// ---------------- generic helpers ----------------
__device__ __forceinline__ float wsum(float v){
    v += __shfl_xor_sync(0xffffffffu, v, 16);
    v += __shfl_xor_sync(0xffffffffu, v, 8);
    v += __shfl_xor_sync(0xffffffffu, v, 4);
    v += __shfl_xor_sync(0xffffffffu, v, 2);
    v += __shfl_xor_sync(0xffffffffu, v, 1);
    return v;
}
__device__ __forceinline__ float softplusf(float x){
    if (x > 20.f) return x;
    return log1pf(expf(x));
}
__device__ __forceinline__ uint32_t smem_u32(const void* p){
    uint32_t a;
    asm("{ .reg .u64 t; cvta.to.shared.u64 t, %1; cvt.u32.u64 %0, t; }" : "=r"(a) : "l"(p));
    return a;
}
__device__ __forceinline__ float ex2f(float x){
    float r;
    asm("ex2.approx.f32 %0, %1;" : "=f"(r) : "f"(x));
    return r;
}
__device__ __forceinline__ uint32_t packbf2(float a, float b){
    __nv_bfloat162 h = __floats2bfloat162_rn(a, b);
    return *(uint32_t*)&h;
}

// ---------------- cp.async helpers (sm_80+ baseline) ----------------
__device__ __forceinline__ void cpa16(uint32_t dst, const void* src){
    asm volatile("cp.async.cg.shared.global [%0], [%1], 16;" :: "r"(dst), "l"(src) : "memory");
}
__device__ __forceinline__ void cpa4(uint32_t dst, const void* src){
    asm volatile("cp.async.ca.shared.global [%0], [%1], 4;" :: "r"(dst), "l"(src) : "memory");
}
#define CPA_COMMIT() asm volatile("cp.async.commit_group;" ::: "memory")
#define CPA_WAIT(n)  asm volatile("cp.async.wait_group %0;" :: "n"(n) : "memory")

// ---------------- mma.sync / ldmatrix helpers (baseline PTX, sm_80+) --------
__device__ __forceinline__ void ldm_x4(uint32_t a[4], uint32_t addr){
    asm volatile("ldmatrix.sync.aligned.m8n8.x4.shared.b16 {%0,%1,%2,%3}, [%4];"
        : "=r"(a[0]), "=r"(a[1]), "=r"(a[2]), "=r"(a[3]) : "r"(addr));
}
__device__ __forceinline__ void ldm_x4t(uint32_t a[4], uint32_t addr){
    asm volatile("ldmatrix.sync.aligned.m8n8.x4.trans.shared.b16 {%0,%1,%2,%3}, [%4];"
        : "=r"(a[0]), "=r"(a[1]), "=r"(a[2]), "=r"(a[3]) : "r"(addr));
}
__device__ __forceinline__ void mma16816(float c[4], const uint32_t a[4], const uint32_t b[2]){
    asm volatile("mma.sync.aligned.m16n8k16.row.col.f32.f16.f16.f32 "
        "{%0,%1,%2,%3}, {%4,%5,%6,%7}, {%8,%9}, {%0,%1,%2,%3};"
        : "+f"(c[0]), "+f"(c[1]), "+f"(c[2]), "+f"(c[3])
        : "r"(a[0]), "r"(a[1]), "r"(a[2]), "r"(a[3]), "r"(b[0]), "r"(b[1]));
}
__device__ __forceinline__ void mma16816bf(float c[4], const uint32_t a[4], const uint32_t b[2]){
    asm volatile("mma.sync.aligned.m16n8k16.row.col.f32.bf16.bf16.f32 "
        "{%0,%1,%2,%3}, {%4,%5,%6,%7}, {%8,%9}, {%0,%1,%2,%3};"
        : "+f"(c[0]), "+f"(c[1]), "+f"(c[2]), "+f"(c[3])
        : "r"(a[0]), "r"(a[1]), "r"(a[2]), "r"(a[3]), "r"(b[0]), "r"(b[1]));
}

// ---------------- k_prep: LN (blocks 0..2047) + weight fold (blocks 2048+) --
__global__ __launch_bounds__(256) void k_prep(const float* __restrict__ x,
                       const float* __restrict__ g, const float* __restrict__ be,
                       const float* __restrict__ wq_w, const float* __restrict__ wq_b,
                       const float* __restrict__ wk_w, const float* __restrict__ wk_b,
                       const float* __restrict__ wv_w, const float* __restrict__ wv_b,
                       const float* __restrict__ mq_w, const float* __restrict__ mq_b,
                       const float* __restrict__ mk_w, const float* __restrict__ mk_b,
                       const float* __restrict__ ow){
    int t = threadIdx.x;
    if (blockIdx.x < 2048){
        int lane = t & 31, w = t >> 5;
        size_t row = (size_t)blockIdx.x*8 + w;
        const float* xr = x + row*64;
        float x0 = xr[lane], x1 = xr[lane+32];
        float mean = wsum(x0+x1)*(1.f/64.f);
        float msq  = wsum(x0*x0+x1*x1)*(1.f/64.f);
        float rs = rsqrtf(msq - mean*mean + 1e-5f);
        __half* o = g_xh + row*64;
        o[lane]    = __float2half_rn((x0-mean)*rs*g[lane]    + be[lane]);
        o[lane+32] = __float2half_rn((x1-mean)*rs*g[lane+32] + be[lane+32]);
        return;
    }
    int r = (blockIdx.x - 2048)*4 + (t >> 6);
    int e = t & 63;
    if (r < 256){
        float acc = 0.f;
        for (int c = 0; c < 256; c++) acc += mq_w[r*256+c]*wq_w[c*64+e];
        g_Wh[r*64+e] = __float2half_rn(acc);
        if (e == 0){
            float bb = mq_b[r];
            for (int c = 0; c < 256; c++) bb += mq_w[r*256+c]*wq_b[c];
            g_bp[r] = bb;
        }
    } else if (r < 512){
        int rr = r - 256;
        float acc = 0.f;
        for (int c = 0; c < 256; c++) acc += mk_w[rr*256+c]*wk_w[c*64+e];
        g_Wh[r*64+e] = __float2half_rn(acc);
        if (e == 0){
            float bb = mk_b[rr];
            for (int c = 0; c < 256; c++) bb += mk_w[rr*256+c]*wk_b[c];
            g_bp[r] = bb;
        }
    } else if (r < 576){
        int rr = r - 512;
        float acc = 0.f;
        for (int d = 0; d < 256; d++) acc += ow[rr*256+d]*wv_w[d*64+e];
        g_Wh[r*64+e] = __float2half_rn(acc);
        if (e == 0){
            float bb = 0.f;
            for (int d = 0; d < 256; d++) bb += ow[rr*256+d]*wv_b[d];
            g_bp[r] = bb;
        }
    } else if (r < 768){
        g_Wh[r*64+e] = __float2half_rn(0.f);
        if (e == 0) g_bp[r] = 0.f;
    }
}

// ---------------- k_qkv: HMMA GEMM, grid (256,3): y=0 Q, y=1 K, y=2 Vo -------
__global__ __launch_bounds__(256) void k_qkv(){
    __shared__ __half sA[64*72];    // pitch 144 B
    __shared__ __half sB[256*72];
    int t = threadIdx.x, lane = t & 31, wid = t >> 5;
    int t4 = lane & 3, gq = lane >> 2;
    int wq = wid & 1, wd = wid >> 1;
    int m0 = blockIdx.x*64;
    int ny = blockIdx.y;
    uint32_t sa = smem_u32(sA), sbb = smem_u32(sB);
    for (int i = t; i < 512; i += 256){
        int r = i >> 3, c = i & 7;
        *(uint4*)((char*)sA + r*144 + c*16) =
            *(const uint4*)((const char*)(g_xh + ((size_t)(m0+r))*64) + c*16);
    }
    for (int i = t; i < 2048; i += 256){
        int r = i >> 3, c = i & 7;
        *(uint4*)((char*)sB + r*144 + c*16) =
            *(const uint4*)((const char*)(g_Wh + (size_t)(ny*256 + r)*64) + c*16);
    }
    __syncthreads();
    uint32_t lo16 = lane & 15, hi16 = lane >> 4;
    uint32_t aQb = sa + (uint32_t)(wq*32 + lo16)*144 + hi16*16;
    uint32_t kl  = (uint32_t)((lane & 7) + ((lane >> 4) << 3));
    uint32_t bWb = sbb + (uint32_t)(wd*64)*144 + kl*144 + (uint32_t)((lane >> 3) & 1)*16;

    float out[2][8][4] = {};
    #pragma unroll
    for (int ks = 0; ks < 4; ks++){
        uint32_t hk = (uint32_t)ks*32;
        uint32_t aq[2][4];
        ldm_x4(aq[0], aQb + hk);
        ldm_x4(aq[1], aQb + 16u*144 + hk);
        #pragma unroll
        for (int ng = 0; ng < 4; ng++){
            uint32_t kf[4];
            ldm_x4(kf, bWb + (uint32_t)(ng*16)*144 + hk);
            #pragma unroll
            for (int mb = 0; mb < 2; mb++){
                mma16816(out[mb][ng*2],   aq[mb], kf);
                mma16816(out[mb][ng*2+1], aq[mb], kf+2);
            }
        }
    }
    const float* bp = g_bp + ny*256;
    if (ny < 2){
        __half* dst = (ny == 0) ? g_q : g_k;
        #pragma unroll
        for (int mb = 0; mb < 2; mb++){
            size_t rA = (size_t)m0 + (size_t)(wq*32 + mb*16 + gq);
            size_t rB = rA + 8;
            #pragma unroll
            for (int nt = 0; nt < 8; nt++){
                int col = wd*64 + nt*8 + 2*t4;
                float b0 = bp[col], b1 = bp[col+1];
                __half2 hA = __floats2half2_rn(out[mb][nt][0] + b0, out[mb][nt][1] + b1);
                __half2 hB = __floats2half2_rn(out[mb][nt][2] + b0, out[mb][nt][3] + b1);
                *(__half2*)&dst[rA*256 + col] = hA;
                *(__half2*)&dst[rB*256 + col] = hB;
            }
        }
    } else if (wd == 0){
        #pragma unroll
        for (int mb = 0; mb < 2; mb++){
            size_t rA = (size_t)m0 + (size_t)(wq*32 + mb*16 + gq);
            size_t rB = rA + 8;
            #pragma unroll
            for (int nt = 0; nt < 8; nt++){
                int col = nt*8 + 2*t4;
                float b0 = bp[col], b1 = bp[col+1];
                uint32_t pA = packbf2(out[mb][nt][0] + b0, out[mb][nt][1] + b1);
                uint32_t pB = packbf2(out[mb][nt][2] + b0, out[mb][nt][3] + b1);
                *(uint32_t*)&g_vo[rA*64 + col] = pA;
                *(uint32_t*)&g_vo[rB*64 + col] = pB;
            }
        }
    }
}

// ---------------- k_attn: fused score+softmax+AV ----------------------------
// 256 threads = 8 warps: wq = wid&1 (32-row group), wh = wid>>1 (head 0..3)
// ks-outer loop: Q fragments loaded once per ks, reused across both 16-key blocks.
#define AT_SQO 0
#define AT_SK0 33792
#define AT_SK1 50688
#define AT_SV0 67584
#define AT_SV1 72192
#define AT_SW0 76800
#define AT_SW1 76928
#define AT_SLO 77056
#define AT_SLW 78080
#define AT_SMEM 79104

__global__ void __launch_bounds__(256,2) k_attn(const float* __restrict__ gw){
    extern __shared__ char sm[];
    uint32_t sb = smem_u32(sm);
    int t = threadIdx.x, lane = t & 31, wid = t >> 5;
    int t4 = lane & 3, gq = lane >> 2;
    int wq = wid & 1, wh = wid >> 1;
    int b = blockIdx.x >> 5, qt = blockIdx.x & 31;
    size_t qrow0 = (size_t)b*NN + (size_t)qt*64;
    const char*  qg  = (const char*)(g_q + qrow0*256);
    const char*  kgb = (const char*)(g_k + (size_t)b*NN*256);
    const char*  vgb = (const char*)(g_vo + (size_t)b*NN*64);
    const float* wb  = gw + (size_t)b*NN;
    float* sL = (float*)(sm + AT_SLO);
    float* sLW = (float*)(sm + AT_SLW);

    // prefetch K tile 0 (32 keys x 512B), Vo tile 0 (32 x 128B), w tile 0
    for (int i = t; i < 1024; i += 256){
        int r = i >> 5, c = i & 31;
        cpa16(sb + AT_SK0 + r*528 + c*16, kgb + (size_t)r*512 + c*16);
    }
    {
        int r = t >> 3, c = t & 7;
        cpa16(sb + AT_SV0 + r*144 + c*16, vgb + (size_t)r*128 + c*16);
    }
    if (t < 32) cpa4(sb + AT_SW0 + t*4, wb + t);
    CPA_COMMIT();
    // Q tile resident (64 x 512B, pitch 528)
    for (int i = t; i < 2048; i += 256){
        int r = i >> 5, c = i & 31;
        *(uint4*)(sm + AT_SQO + r*528 + c*16) = *(const uint4*)(qg + r*512 + c*16);
    }

    uint32_t lo16 = lane & 15, hi16 = lane >> 4;
    uint32_t aQb = sb + AT_SQO + (uint32_t)(wq*32 + lo16)*528 + hi16*16;
    uint32_t kl  = (uint32_t)((lane & 7) + ((lane >> 4) << 3));

    float out[2][8][4];
    #pragma unroll
    for (int mb = 0; mb < 2; mb++)
        #pragma unroll
        for (int nt = 0; nt < 8; nt++)
            #pragma unroll
            for (int q = 0; q < 4; q++) out[mb][nt][q] = 0.f;
    float lacc[2][2], lwac[2][2];
    #pragma unroll
    for (int mb = 0; mb < 2; mb++)
        #pragma unroll
        for (int hf = 0; hf < 2; hf++){ lacc[mb][hf] = 0.f; lwac[mb][hf] = 0.f; }

    for (int jt = 0; jt < 64; jt++){
        uint32_t koff = (jt & 1) ? AT_SK1 : AT_SK0;
        uint32_t voff = (jt & 1) ? AT_SV1 : AT_SV0;
        uint32_t woff = (jt & 1) ? AT_SW1 : AT_SW0;
        if (jt < 63){
            uint32_t kn = (jt & 1) ? AT_SK0 : AT_SK1;
            uint32_t vn = (jt & 1) ? AT_SV0 : AT_SV1;
            uint32_t wn = (jt & 1) ? AT_SW0 : AT_SW1;
            const char* ksrc = kgb + (size_t)(jt+1)*16384;
            const char* vsrc = vgb + (size_t)(jt+1)*4096;
            for (int i = t; i < 1024; i += 256){
                int r = i >> 5, c = i & 31;
                cpa16(sb + kn + r*528 + c*16, ksrc + (size_t)r*512 + c*16);
            }
            {
                int r = t >> 3, c = t & 7;
                cpa16(sb + vn + r*144 + c*16, vsrc + (size_t)r*128 + c*16);
            }
            if (t < 32) cpa4(sb + wn + t*4, wb + (jt+1)*32 + t);
            CPA_COMMIT();
            CPA_WAIT(1);
        } else {
            CPA_WAIT(0);
        }
        __syncthreads();
        const float* sw = (const float*)(sm + woff);
        uint32_t bK = sb + koff + kl*528 + (uint32_t)((lane >> 3) & 1)*16;
        uint32_t bV = sb + voff + lo16*144 + hi16*16;

        // ---- scores for both 16-key blocks, Q frags loaded once per ks ----
        float sacc[2][2][2][4];   // [kb][mb][nt][4]
        #pragma unroll
        for (int kb = 0; kb < 2; kb++)
            #pragma unroll
            for (int mb = 0; mb < 2; mb++)
                #pragma unroll
                for (int nt = 0; nt < 2; nt++)
                    #pragma unroll
                    for (int q = 0; q < 4; q++) sacc[kb][mb][nt][q] = 0.f;
        #pragma unroll
        for (int ks = 0; ks < 4; ks++){
            uint32_t hk = (uint32_t)(wh*64 + ks*16)*2;
            uint32_t aq0[4], aq1[4];
            ldm_x4(aq0, aQb + hk);
            ldm_x4(aq1, aQb + 16u*528 + hk);
            #pragma unroll
            for (int kb = 0; kb < 2; kb++){
                uint32_t kf[4];
                ldm_x4(kf, bK + (uint32_t)(kb*16)*528 + hk);
                mma16816(sacc[kb][0][0], aq0, kf);
                mma16816(sacc[kb][0][1], aq0, kf+2);
                mma16816(sacc[kb][1][0], aq1, kf);
                mma16816(sacc[kb][1][1], aq1, kf+2);
            }
        }
        // ---- per-block softmax terms + fused AV ----
        #pragma unroll
        for (int kb = 0; kb < 2; kb++){
            float wv[4], mv[4];
            #pragma unroll
            for (int nt = 0; nt < 2; nt++){
                int kloc = kb*16 + nt*8 + 2*t4;
                wv[2*nt]   = sw[kloc];
                wv[2*nt+1] = sw[kloc+1];
                mv[2*nt]   = (wv[2*nt]   != 0.f) ? 1.f : 0.f;
                mv[2*nt+1] = (wv[2*nt+1] != 0.f) ? 1.f : 0.f;
            }
            uint32_t pk2[2][4];
            #pragma unroll
            for (int mb = 0; mb < 2; mb++){
                #pragma unroll
                for (int nt = 0; nt < 2; nt++){
                    float e0 = ex2f(sacc[kb][mb][nt][0]*CEXP);
                    float e1 = ex2f(sacc[kb][mb][nt][1]*CEXP);
                    float e2 = ex2f(sacc[kb][mb][nt][2]*CEXP);
                    float e3 = ex2f(sacc[kb][mb][nt][3]*CEXP);
                    lacc[mb][0] = fmaf(e0, mv[2*nt], fmaf(e1, mv[2*nt+1], lacc[mb][0]));
                    lacc[mb][1] = fmaf(e2, mv[2*nt], fmaf(e3, mv[2*nt+1], lacc[mb][1]));
                    float ew0 = e0*wv[2*nt], ew1 = e1*wv[2*nt+1];
                    float ew2 = e2*wv[2*nt], ew3 = e3*wv[2*nt+1];
                    lwac[mb][0] += ew0 + ew1;
                    lwac[mb][1] += ew2 + ew3;
                    pk2[mb][nt*2]   = packbf2(ew0, ew1);
                    pk2[mb][nt*2+1] = packbf2(ew2, ew3);
                }
            }
            #pragma unroll
            for (int dt2 = 0; dt2 < 4; dt2++){
                uint32_t vf[4];
                ldm_x4t(vf, bV + (uint32_t)(kb*16)*144 + (uint32_t)dt2*32);
                mma16816bf(out[0][dt2*2],   pk2[0], vf);
                mma16816bf(out[0][dt2*2+1], pk2[0], vf+2);
                mma16816bf(out[1][dt2*2],   pk2[1], vf);
                mma16816bf(out[1][dt2*2+1], pk2[1], vf+2);
            }
        }
        __syncthreads();
    }
    // quad-reduce l, lw; single writer per (row, head)
    #pragma unroll
    for (int mb = 0; mb < 2; mb++)
        #pragma unroll
        for (int hf = 0; hf < 2; hf++){
            float v = lacc[mb][hf];
            v += __shfl_xor_sync(0xffffffffu, v, 1);
            v += __shfl_xor_sync(0xffffffffu, v, 2);
            float u = lwac[mb][hf];
            u += __shfl_xor_sync(0xffffffffu, u, 1);
            u += __shfl_xor_sync(0xffffffffu, u, 2);
            if (t4 == 0){
                int row = wq*32 + mb*16 + hf*8 + gq;
                sL[row*4 + wh] = v;
                sLW[row*4 + wh] = u;
            }
        }
    __syncthreads();
    // scale by il_h, dump per-head planes into reduction overlay [0,64KB)
    float* red = (float*)sm;
    #pragma unroll
    for (int mb = 0; mb < 2; mb++){
        int rA = wq*32 + mb*16 + gq;
        int rB = rA + 8;
        float ilA = 1.f / sL[rA*4 + wh];
        float ilB = 1.f / sL[rB*4 + wh];
        #pragma unroll
        for (int nt = 0; nt < 8; nt++){
            int col = nt*8 + 2*t4;
            *(float2*)&red[(wh*64 + rA)*64 + col] = make_float2(out[mb][nt][0]*ilA, out[mb][nt][1]*ilA);
            *(float2*)&red[(wh*64 + rB)*64 + col] = make_float2(out[mb][nt][2]*ilB, out[mb][nt][3]*ilB);
        }
    }
    __syncthreads();
    for (int i = t; i < 1024; i += 256){
        int row = i >> 4, c4 = (i & 15)*4;
        float4 s0 = *(const float4*)&red[(row)*64 + c4];
        float4 s1 = *(const float4*)&red[(64 + row)*64 + c4];
        float4 s2 = *(const float4*)&red[(128 + row)*64 + c4];
        float4 s3 = *(const float4*)&red[(192 + row)*64 + c4];
        float z = sLW[row*4+0]/sL[row*4+0] + sLW[row*4+1]/sL[row*4+1]
                + sLW[row*4+2]/sL[row*4+2] + sLW[row*4+3]/sL[row*4+3];
        float iz = 1.f / z;
        float4 o = make_float4((s0.x+s1.x+s2.x+s3.x)*iz, (s0.y+s1.y+s2.y+s3.y)*iz,
                               (s0.z+s1.z+s2.z+s3.z)*iz, (s0.w+s1.w+s2.w+s3.w)*iz);
        *(float4*)&g_av[(qrow0 + (size_t)row)*64 + c4] = o;
    }
}

// ---------------- k_tail: out1 = x + av + ob; out = LN(out1 + sp(LN(out1)@fw^T + fb))
__global__ __launch_bounds__(256) void k_tail(const float* __restrict__ ob,
                                              const float* __restrict__ x,
                                              const float* __restrict__ g,
                                              const float* __restrict__ be,
                                              const float* __restrict__ fw,
                                              const float* __restrict__ fb,
                                              float* __restrict__ out){
    __shared__ float sA[64*68];
    __shared__ float sB[64*68];
    __shared__ float sy[8][64];
    int m0 = blockIdx.x*64;
    int t = threadIdx.x, lane = t & 31, w = t >> 5;
    for (int i = t; i < 1024; i += 256){
        int r = i >> 4, c = i & 15;
        float4 xv = *(const float4*)&x[((size_t)(m0+r))*64 + c*4];
        float4 av = *(const float4*)&g_av[((size_t)(m0+r))*64 + c*4];
        float4 obv = *(const float4*)&ob[c*4];
        sA[r*68 + c*4 + 0] = xv.x + av.x + obv.x;
        sA[r*68 + c*4 + 1] = xv.y + av.y + obv.y;
        sA[r*68 + c*4 + 2] = xv.z + av.z + obv.z;
        sA[r*68 + c*4 + 3] = xv.w + av.w + obv.w;
    }
    for (int i = t; i < 4096; i += 256) sB[(i>>6)*65 + (i&63)] = fw[i];
    __syncthreads();
    #pragma unroll 1
    for (int rr = 0; rr < 8; rr++){
        int rl = w*8 + rr;
        float o0 = sA[rl*68 + lane], o1 = sA[rl*68 + lane + 32];
        float mean = wsum(o0+o1)*(1.f/64.f);
        float msq  = wsum(o0*o0+o1*o1)*(1.f/64.f);
        float rs = rsqrtf(msq - mean*mean + 1e-5f);
        sy[w][lane]    = (o0-mean)*rs*g[lane]    + be[lane];
        sy[w][lane+32] = (o1-mean)*rs*g[lane+32] + be[lane+32];
        __syncwarp();
        float a0 = fb[lane], a1 = fb[lane+32];
        #pragma unroll 8
        for (int c = 0; c < 64; c++){
            float yv = sy[w][c];
            a0 += yv * sB[lane*65 + c];
            a1 += yv * sB[(lane+32)*65 + c];
        }
        float s0 = o0 + softplusf(a0);
        float s1 = o1 + softplusf(a1);
        float m2 = wsum(s0+s1)*(1.f/64.f);
        float q2 = wsum(s0*s0+s1*s1)*(1.f/64.f);
        float r2 = rsqrtf(q2 - m2*m2 + 1e-5f);
        size_t m = m0 + rl;
        out[m*64 + lane]    = (s0-m2)*r2*g[lane]    + be[lane];
        out[m*64 + lane+32] = (s1-m2)*r2*g[lane+32] + be[lane+32];
        __syncwarp();
    }
}

// ---------------- launch ----------------
extern "C" void kernel_launch(void* const* d_in, const int* in_sizes, int n_in,
                              void* d_out, int out_size){
    (void)in_sizes; (void)n_in; (void)out_size;
    const float* x     = (const float*)d_in[0];
    const float* wts   = (const float*)d_in[1];
    const float* ln_g  = (const float*)d_in[2];
    const float* ln_b  = (const float*)d_in[3];
    const float* wq_w  = (const float*)d_in[4];
    const float* wq_b  = (const float*)d_in[5];
    const float* wk_w  = (const float*)d_in[6];
    const float* wk_b  = (const float*)d_in[7];
    const float* wv_w  = (const float*)d_in[8];
    const float* wv_b  = (const float*)d_in[9];
    const float* mq_w  = (const float*)d_in[10];
    const float* mq_b  = (const float*)d_in[11];
    const float* mk_w  = (const float*)d_in[12];
    const float* mk_b  = (const float*)d_in[13];
    const float* out_w = (const float*)d_in[14];
    const float* out_b = (const float*)d_in[15];
    const float* ffn_w = (const float*)d_in[16];
    const float* ffn_b = (const float*)d_in[17];
    float* out = (float*)d_out;

    cudaFuncSetAttribute(k_attn, cudaFuncAttributeMaxDynamicSharedMemorySize, AT_SMEM);

    k_prep<<<2048 + 192, 256>>>(x, ln_g, ln_b, wq_w, wq_b, wk_w, wk_b, wv_w, wv_b,
                                mq_w, mq_b, mk_w, mk_b, out_w);
    k_qkv<<<dim3(ROWS/64, 3), 256>>>();
    k_attn<<<256, 256, AT_SMEM>>>(wts);
    k_tail<<<ROWS/64, 256>>>(out_b, x, ln_g, ln_b, ffn_w, ffn_b, out);
}

// round 15
// speedup vs baseline: 1.2524x; 1.0177x over previous
#include <cuda_runtime.h>
#include <cuda_fp16.h>
#include <cuda_bf16.h>
#include <math.h>
#include <stdint.h>

#define BB 8
#define NN 2048
#define EE 64
#define DD 256
#define ROWS (BB*NN)   // 16384

// ---------------- scratch (static device globals; no allocs) ----------------
__device__ __align__(16) __half g_xh[ROWS*EE];            // LN(x) in fp16
__device__ __align__(16) __half g_q[ROWS*DD];
__device__ __align__(16) __half g_k[ROWS*DD];
__device__ __align__(16) __nv_bfloat16 g_vo[ROWS*EE];     // V @ ow^T (+ ow@wvb), bf16
__device__ __align__(16) __half g_Wh[768*64];              // folded weights
__device__ float g_bp[768];

#define CEXP 0.18033688f   // 0.125 * log2(e)

// ---------------- generic helpers ----------------
__device__ __forceinline__ float wsum(float v){
    v += __shfl_xor_sync(0xffffffffu, v, 16);
    v += __shfl_xor_sync(0xffffffffu, v, 8);
    v += __shfl_xor_sync(0xffffffffu, v, 4);
    v += __shfl_xor_sync(0xffffffffu, v, 2);
    v += __shfl_xor_sync(0xffffffffu, v, 1);
    return v;
}
__device__ __forceinline__ uint32_t smem_u32(const void* p){
    uint32_t a;
    asm("{ .reg .u64 t; cvta.to.shared.u64 t, %1; cvt.u32.u64 %0, t; }" : "=r"(a) : "l"(p));
    return a;
}
__device__ __forceinline__ float ex2f(float x){
    float r;
    asm("ex2.approx.f32 %0, %1;" : "=f"(r) : "f"(x));
    return r;
}
__device__ __forceinline__ float lg2f(float x){
    float r;
    asm("lg2.approx.f32 %0, %1;" : "=f"(r) : "f"(x));
    return r;
}
__device__ __forceinline__ float softplus_fast(float x){
    if (x > 20.f) return x;
    return lg2f(1.f + ex2f(x * 1.44269504f)) * 0.69314718f;
}
__device__ __forceinline__ uint32_t packbf2(float a, float b){
    __nv_bfloat162 h = __floats2bfloat162_rn(a, b);
    return *(uint32_t*)&h;
}

// ---------------- cp.async helpers (sm_80+ baseline) ----------------
__device__ __forceinline__ void cpa16(uint32_t dst, const void* src){
    asm volatile("cp.async.cg.shared.global [%0], [%1], 16;" :: "r"(dst), "l"(src) : "memory");
}
__device__ __forceinline__ void cpa4(uint32_t dst, const void* src){
    asm volatile("cp.async.ca.shared.global [%0], [%1], 4;" :: "r"(dst), "l"(src) : "memory");
}
#define CPA_COMMIT() asm volatile("cp.async.commit_group;" ::: "memory")
#define CPA_WAIT(n)  asm volatile("cp.async.wait_group %0;" :: "n"(n) : "memory")

// ---------------- mma.sync / ldmatrix helpers (baseline PTX, sm_80+) --------
__device__ __forceinline__ void ldm_x4(uint32_t a[4], uint32_t addr){
    asm volatile("ldmatrix.sync.aligned.m8n8.x4.shared.b16 {%0,%1,%2,%3}, [%4];"
        : "=r"(a[0]), "=r"(a[1]), "=r"(a[2]), "=r"(a[3]) : "r"(addr));
}
__device__ __forceinline__ void ldm_x4t(uint32_t a[4], uint32_t addr){
    asm volatile("ldmatrix.sync.aligned.m8n8.x4.trans.shared.b16 {%0,%1,%2,%3}, [%4];"
        : "=r"(a[0]), "=r"(a[1]), "=r"(a[2]), "=r"(a[3]) : "r"(addr));
}
__device__ __forceinline__ void mma16816(float c[4], const uint32_t a[4], const uint32_t b[2]){
    asm volatile("mma.sync.aligned.m16n8k16.row.col.f32.f16.f16.f32 "
        "{%0,%1,%2,%3}, {%4,%5,%6,%7}, {%8,%9}, {%0,%1,%2,%3};"
        : "+f"(c[0]), "+f"(c[1]), "+f"(c[2]), "+f"(c[3])
        : "r"(a[0]), "r"(a[1]), "r"(a[2]), "r"(a[3]), "r"(b[0]), "r"(b[1]));
}
__device__ __forceinline__ void mma16816bf(float c[4], const uint32_t a[4], const uint32_t b[2]){
    asm volatile("mma.sync.aligned.m16n8k16.row.col.f32.bf16.bf16.f32 "
        "{%0,%1,%2,%3}, {%4,%5,%6,%7}, {%8,%9}, {%0,%1,%2,%3};"
        : "+f"(c[0]), "+f"(c[1]), "+f"(c[2]), "+f"(c[3])
        : "r"(a[0]), "r"(a[1]), "r"(a[2]), "r"(a[3]), "r"(b[0]), "r"(b[1]));
}

// ---------------- k_prep: LN (blocks 0..2047) + weight fold (blocks 2048+) --
__global__ __launch_bounds__(256) void k_prep(const float* __restrict__ x,
                       const float* __restrict__ g, const float* __restrict__ be,
                       const float* __restrict__ wq_w, const float* __restrict__ wq_b,
                       const float* __restrict__ wk_w, const float* __restrict__ wk_b,
                       const float* __restrict__ wv_w, const float* __restrict__ wv_b,
                       const float* __restrict__ mq_w, const float* __restrict__ mq_b,
                       const float* __restrict__ mk_w, const float* __restrict__ mk_b,
                       const float* __restrict__ ow){
    int t = threadIdx.x;
    if (blockIdx.x < 2048){
        int lane = t & 31, w = t >> 5;
        size_t row = (size_t)blockIdx.x*8 + w;
        const float* xr = x + row*64;
        float x0 = xr[lane], x1 = xr[lane+32];
        float mean = wsum(x0+x1)*(1.f/64.f);
        float msq  = wsum(x0*x0+x1*x1)*(1.f/64.f);
        float rs = rsqrtf(msq - mean*mean + 1e-5f);
        __half* o = g_xh + row*64;
        o[lane]    = __float2half_rn((x0-mean)*rs*g[lane]    + be[lane]);
        o[lane+32] = __float2half_rn((x1-mean)*rs*g[lane+32] + be[lane+32]);
        return;
    }
    int r = (blockIdx.x - 2048)*4 + (t >> 6);
    int e = t & 63;
    if (r < 256){
        float acc = 0.f;
        for (int c = 0; c < 256; c++) acc += mq_w[r*256+c]*wq_w[c*64+e];
        g_Wh[r*64+e] = __float2half_rn(acc);
        if (e == 0){
            float bb = mq_b[r];
            for (int c = 0; c < 256; c++) bb += mq_w[r*256+c]*wq_b[c];
            g_bp[r] = bb;
        }
    } else if (r < 512){
        int rr = r - 256;
        float acc = 0.f;
        for (int c = 0; c < 256; c++) acc += mk_w[rr*256+c]*wk_w[c*64+e];
        g_Wh[r*64+e] = __float2half_rn(acc);
        if (e == 0){
            float bb = mk_b[rr];
            for (int c = 0; c < 256; c++) bb += mk_w[rr*256+c]*wk_b[c];
            g_bp[r] = bb;
        }
    } else if (r < 576){
        int rr = r - 512;
        float acc = 0.f;
        for (int d = 0; d < 256; d++) acc += ow[rr*256+d]*wv_w[d*64+e];
        g_Wh[r*64+e] = __float2half_rn(acc);
        if (e == 0){
            float bb = 0.f;
            for (int d = 0; d < 256; d++) bb += ow[rr*256+d]*wv_b[d];
            g_bp[r] = bb;
        }
    } else if (r < 768){
        g_Wh[r*64+e] = __float2half_rn(0.f);
        if (e == 0) g_bp[r] = 0.f;
    }
}

// ---------------- k_qkv: HMMA GEMM, grid (256,3): y=0 Q, y=1 K, y=2 Vo -------
__global__ __launch_bounds__(256) void k_qkv(){
    __shared__ __half sA[64*72];    // pitch 144 B
    __shared__ __half sB[256*72];
    int t = threadIdx.x, lane = t & 31, wid = t >> 5;
    int t4 = lane & 3, gq = lane >> 2;
    int wq = wid & 1, wd = wid >> 1;
    int m0 = blockIdx.x*64;
    int ny = blockIdx.y;
    uint32_t sa = smem_u32(sA), sbb = smem_u32(sB);
    for (int i = t; i < 512; i += 256){
        int r = i >> 3, c = i & 7;
        *(uint4*)((char*)sA + r*144 + c*16) =
            *(const uint4*)((const char*)(g_xh + ((size_t)(m0+r))*64) + c*16);
    }
    for (int i = t; i < 2048; i += 256){
        int r = i >> 3, c = i & 7;
        *(uint4*)((char*)sB + r*144 + c*16) =
            *(const uint4*)((const char*)(g_Wh + (size_t)(ny*256 + r)*64) + c*16);
    }
    __syncthreads();
    uint32_t lo16 = lane & 15, hi16 = lane >> 4;
    uint32_t aQb = sa + (uint32_t)(wq*32 + lo16)*144 + hi16*16;
    uint32_t kl  = (uint32_t)((lane & 7) + ((lane >> 4) << 3));
    uint32_t bWb = sbb + (uint32_t)(wd*64)*144 + kl*144 + (uint32_t)((lane >> 3) & 1)*16;

    float out[2][8][4] = {};
    #pragma unroll
    for (int ks = 0; ks < 4; ks++){
        uint32_t hk = (uint32_t)ks*32;
        uint32_t aq[2][4];
        ldm_x4(aq[0], aQb + hk);
        ldm_x4(aq[1], aQb + 16u*144 + hk);
        #pragma unroll
        for (int ng = 0; ng < 4; ng++){
            uint32_t kf[4];
            ldm_x4(kf, bWb + (uint32_t)(ng*16)*144 + hk);
            #pragma unroll
            for (int mb = 0; mb < 2; mb++){
                mma16816(out[mb][ng*2],   aq[mb], kf);
                mma16816(out[mb][ng*2+1], aq[mb], kf+2);
            }
        }
    }
    const float* bp = g_bp + ny*256;
    if (ny < 2){
        __half* dst = (ny == 0) ? g_q : g_k;
        #pragma unroll
        for (int mb = 0; mb < 2; mb++){
            size_t rA = (size_t)m0 + (size_t)(wq*32 + mb*16 + gq);
            size_t rB = rA + 8;
            #pragma unroll
            for (int nt = 0; nt < 8; nt++){
                int col = wd*64 + nt*8 + 2*t4;
                float b0 = bp[col], b1 = bp[col+1];
                __half2 hA = __floats2half2_rn(out[mb][nt][0] + b0, out[mb][nt][1] + b1);
                __half2 hB = __floats2half2_rn(out[mb][nt][2] + b0, out[mb][nt][3] + b1);
                *(__half2*)&dst[rA*256 + col] = hA;
                *(__half2*)&dst[rB*256 + col] = hB;
            }
        }
    } else if (wd == 0){
        #pragma unroll
        for (int mb = 0; mb < 2; mb++){
            size_t rA = (size_t)m0 + (size_t)(wq*32 + mb*16 + gq);
            size_t rB = rA + 8;
            #pragma unroll
            for (int nt = 0; nt < 8; nt++){
                int col = nt*8 + 2*t4;
                float b0 = bp[col], b1 = bp[col+1];
                uint32_t pA = packbf2(out[mb][nt][0] + b0, out[mb][nt][1] + b1);
                uint32_t pB = packbf2(out[mb][nt][2] + b0, out[mb][nt][3] + b1);
                *(uint32_t*)&g_vo[rA*64 + col] = pA;
                *(uint32_t*)&g_vo[rB*64 + col] = pB;
            }
        }
    }
}

// ---------------- k_attn: fused score+softmax+AV + residual/LN/FFN tail -----
// 256 threads = 8 warps: wq = wid&1 (32-row group), wh = wid>>1 (head 0..3)
#define AT_SQO 0
#define AT_SK0 33792
#define AT_SK1 50688
#define AT_SV0 67584
#define AT_SV1 72192
#define AT_SW0 76800
#define AT_SW1 76928
#define AT_SLO 77056
#define AT_SLW 78080
#define AT_SMEM 79104
// epilogue overlays (red planes 4x64x64 fp32 = 64KB at [0,65536));
// then out1 [0,17408) pitch 68, fw [17408,34048) pitch 65, sy [34048,36096)
#define EP_O1  0
#define EP_FW  17408
#define EP_SY  34048

__global__ void __launch_bounds__(256,2) k_attn(const float* __restrict__ gw,
                                                const float* __restrict__ xin,
                                                const float* __restrict__ ob,
                                                const float* __restrict__ lng,
                                                const float* __restrict__ lnb,
                                                const float* __restrict__ fw,
                                                const float* __restrict__ fb,
                                                float* __restrict__ outp){
    extern __shared__ char sm[];
    uint32_t sb = smem_u32(sm);
    int t = threadIdx.x, lane = t & 31, wid = t >> 5;
    int t4 = lane & 3, gq = lane >> 2;
    int wq = wid & 1, wh = wid >> 1;
    int b = blockIdx.x >> 5, qt = blockIdx.x & 31;
    size_t qrow0 = (size_t)b*NN + (size_t)qt*64;
    const char*  qg  = (const char*)(g_q + qrow0*256);
    const char*  kgb = (const char*)(g_k + (size_t)b*NN*256);
    const char*  vgb = (const char*)(g_vo + (size_t)b*NN*64);
    const float* wb  = gw + (size_t)b*NN;
    float* sL = (float*)(sm + AT_SLO);
    float* sLW = (float*)(sm + AT_SLW);

    // prefetch K tile 0 (32 keys x 512B), Vo tile 0 (32 x 128B), w tile 0
    for (int i = t; i < 1024; i += 256){
        int r = i >> 5, c = i & 31;
        cpa16(sb + AT_SK0 + r*528 + c*16, kgb + (size_t)r*512 + c*16);
    }
    {
        int r = t >> 3, c = t & 7;
        cpa16(sb + AT_SV0 + r*144 + c*16, vgb + (size_t)r*128 + c*16);
    }
    if (t < 32) cpa4(sb + AT_SW0 + t*4, wb + t);
    CPA_COMMIT();
    // Q tile resident (64 x 512B, pitch 528)
    for (int i = t; i < 2048; i += 256){
        int r = i >> 5, c = i & 31;
        *(uint4*)(sm + AT_SQO + r*528 + c*16) = *(const uint4*)(qg + r*512 + c*16);
    }

    uint32_t lo16 = lane & 15, hi16 = lane >> 4;
    uint32_t aQb = sb + AT_SQO + (uint32_t)(wq*32 + lo16)*528 + hi16*16;
    uint32_t kl  = (uint32_t)((lane & 7) + ((lane >> 4) << 3));

    float out[2][8][4];
    #pragma unroll
    for (int mb = 0; mb < 2; mb++)
        #pragma unroll
        for (int nt = 0; nt < 8; nt++)
            #pragma unroll
            for (int q = 0; q < 4; q++) out[mb][nt][q] = 0.f;
    float lacc[2][2], lwac[2][2];
    #pragma unroll
    for (int mb = 0; mb < 2; mb++)
        #pragma unroll
        for (int hf = 0; hf < 2; hf++){ lacc[mb][hf] = 0.f; lwac[mb][hf] = 0.f; }

    for (int jt = 0; jt < 64; jt++){
        uint32_t koff = (jt & 1) ? AT_SK1 : AT_SK0;
        uint32_t voff = (jt & 1) ? AT_SV1 : AT_SV0;
        uint32_t woff = (jt & 1) ? AT_SW1 : AT_SW0;
        if (jt < 63){
            uint32_t kn = (jt & 1) ? AT_SK0 : AT_SK1;
            uint32_t vn = (jt & 1) ? AT_SV0 : AT_SV1;
            uint32_t wn = (jt & 1) ? AT_SW0 : AT_SW1;
            const char* ksrc = kgb + (size_t)(jt+1)*16384;
            const char* vsrc = vgb + (size_t)(jt+1)*4096;
            for (int i = t; i < 1024; i += 256){
                int r = i >> 5, c = i & 31;
                cpa16(sb + kn + r*528 + c*16, ksrc + (size_t)r*512 + c*16);
            }
            {
                int r = t >> 3, c = t & 7;
                cpa16(sb + vn + r*144 + c*16, vsrc + (size_t)r*128 + c*16);
            }
            if (t < 32) cpa4(sb + wn + t*4, wb + (jt+1)*32 + t);
            CPA_COMMIT();
            CPA_WAIT(1);
        } else {
            CPA_WAIT(0);
        }
        __syncthreads();
        const float* sw = (const float*)(sm + woff);
        uint32_t bK = sb + koff + kl*528 + (uint32_t)((lane >> 3) & 1)*16;
        uint32_t bV = sb + voff + lo16*144 + hi16*16;

        float sacc[2][2][2][4];   // [kb][mb][nt][4]
        #pragma unroll
        for (int kb = 0; kb < 2; kb++)
            #pragma unroll
            for (int mb = 0; mb < 2; mb++)
                #pragma unroll
                for (int nt = 0; nt < 2; nt++)
                    #pragma unroll
                    for (int q = 0; q < 4; q++) sacc[kb][mb][nt][q] = 0.f;
        #pragma unroll
        for (int ks = 0; ks < 4; ks++){
            uint32_t hk = (uint32_t)(wh*64 + ks*16)*2;
            uint32_t aq0[4], aq1[4];
            ldm_x4(aq0, aQb + hk);
            ldm_x4(aq1, aQb + 16u*528 + hk);
            #pragma unroll
            for (int kb = 0; kb < 2; kb++){
                uint32_t kf[4];
                ldm_x4(kf, bK + (uint32_t)(kb*16)*528 + hk);
                mma16816(sacc[kb][0][0], aq0, kf);
                mma16816(sacc[kb][0][1], aq0, kf+2);
                mma16816(sacc[kb][1][0], aq1, kf);
                mma16816(sacc[kb][1][1], aq1, kf+2);
            }
        }
        #pragma unroll
        for (int kb = 0; kb < 2; kb++){
            float wv[4], mv[4];
            #pragma unroll
            for (int nt = 0; nt < 2; nt++){
                int kloc = kb*16 + nt*8 + 2*t4;
                wv[2*nt]   = sw[kloc];
                wv[2*nt+1] = sw[kloc+1];
                mv[2*nt]   = (wv[2*nt]   != 0.f) ? 1.f : 0.f;
                mv[2*nt+1] = (wv[2*nt+1] != 0.f) ? 1.f : 0.f;
            }
            uint32_t pk2[2][4];
            #pragma unroll
            for (int mb = 0; mb < 2; mb++){
                #pragma unroll
                for (int nt = 0; nt < 2; nt++){
                    float e0 = ex2f(sacc[kb][mb][nt][0]*CEXP);
                    float e1 = ex2f(sacc[kb][mb][nt][1]*CEXP);
                    float e2 = ex2f(sacc[kb][mb][nt][2]*CEXP);
                    float e3 = ex2f(sacc[kb][mb][nt][3]*CEXP);
                    lacc[mb][0] = fmaf(e0, mv[2*nt], fmaf(e1, mv[2*nt+1], lacc[mb][0]));
                    lacc[mb][1] = fmaf(e2, mv[2*nt], fmaf(e3, mv[2*nt+1], lacc[mb][1]));
                    float ew0 = e0*wv[2*nt], ew1 = e1*wv[2*nt+1];
                    float ew2 = e2*wv[2*nt], ew3 = e3*wv[2*nt+1];
                    lwac[mb][0] += ew0 + ew1;
                    lwac[mb][1] += ew2 + ew3;
                    pk2[mb][nt*2]   = packbf2(ew0, ew1);
                    pk2[mb][nt*2+1] = packbf2(ew2, ew3);
                }
            }
            #pragma unroll
            for (int dt2 = 0; dt2 < 4; dt2++){
                uint32_t vf[4];
                ldm_x4t(vf, bV + (uint32_t)(kb*16)*144 + (uint32_t)dt2*32);
                mma16816bf(out[0][dt2*2],   pk2[0], vf);
                mma16816bf(out[0][dt2*2+1], pk2[0], vf+2);
                mma16816bf(out[1][dt2*2],   pk2[1], vf);
                mma16816bf(out[1][dt2*2+1], pk2[1], vf+2);
            }
        }
        __syncthreads();
    }
    // quad-reduce l, lw; single writer per (row, head)
    #pragma unroll
    for (int mb = 0; mb < 2; mb++)
        #pragma unroll
        for (int hf = 0; hf < 2; hf++){
            float v = lacc[mb][hf];
            v += __shfl_xor_sync(0xffffffffu, v, 1);
            v += __shfl_xor_sync(0xffffffffu, v, 2);
            float u = lwac[mb][hf];
            u += __shfl_xor_sync(0xffffffffu, u, 1);
            u += __shfl_xor_sync(0xffffffffu, u, 2);
            if (t4 == 0){
                int row = wq*32 + mb*16 + hf*8 + gq;
                sL[row*4 + wh] = v;
                sLW[row*4 + wh] = u;
            }
        }
    __syncthreads();
    // scale by il_h, dump per-head planes into reduction overlay [0,64KB)
    float* red = (float*)sm;
    #pragma unroll
    for (int mb = 0; mb < 2; mb++){
        int rA = wq*32 + mb*16 + gq;
        int rB = rA + 8;
        float ilA = 1.f / sL[rA*4 + wh];
        float ilB = 1.f / sL[rB*4 + wh];
        #pragma unroll
        for (int nt = 0; nt < 8; nt++){
            int col = nt*8 + 2*t4;
            *(float2*)&red[(wh*64 + rA)*64 + col] = make_float2(out[mb][nt][0]*ilA, out[mb][nt][1]*ilA);
            *(float2*)&red[(wh*64 + rB)*64 + col] = make_float2(out[mb][nt][2]*ilB, out[mb][nt][3]*ilB);
        }
    }
    __syncthreads();
    // cross-head reduce -> out1 = x + av/z + ob (held in registers)
    float4 o1r[4];
    int rows4[4], cols4[4];
    #pragma unroll
    for (int k = 0; k < 4; k++){
        int i = t + k*256;
        int row = i >> 4, c4 = (i & 15)*4;
        rows4[k] = row; cols4[k] = c4;
        float4 s0 = *(const float4*)&red[(row)*64 + c4];
        float4 s1 = *(const float4*)&red[(64 + row)*64 + c4];
        float4 s2 = *(const float4*)&red[(128 + row)*64 + c4];
        float4 s3 = *(const float4*)&red[(192 + row)*64 + c4];
        float z = sLW[row*4+0]/sL[row*4+0] + sLW[row*4+1]/sL[row*4+1]
                + sLW[row*4+2]/sL[row*4+2] + sLW[row*4+3]/sL[row*4+3];
        float iz = 1.f / z;
        float4 xv = *(const float4*)&xin[(qrow0 + (size_t)row)*64 + c4];
        float4 obv = *(const float4*)&ob[c4];
        o1r[k] = make_float4((s0.x+s1.x+s2.x+s3.x)*iz + xv.x + obv.x,
                             (s0.y+s1.y+s2.y+s3.y)*iz + xv.y + obv.y,
                             (s0.z+s1.z+s2.z+s3.z)*iz + xv.z + obv.z,
                             (s0.w+s1.w+s2.w+s3.w)*iz + xv.w + obv.w);
    }
    __syncthreads();   // all red reads done; overlay is reusable
    float* sO1 = (float*)(sm + EP_O1);   // pitch 68
    float* sFW = (float*)(sm + EP_FW);   // pitch 65
    float* sy  = (float*)(sm + EP_SY);   // [8][64]
    #pragma unroll
    for (int k = 0; k < 4; k++){
        int row = rows4[k], c4 = cols4[k];
        sO1[row*68 + c4 + 0] = o1r[k].x;
        sO1[row*68 + c4 + 1] = o1r[k].y;
        sO1[row*68 + c4 + 2] = o1r[k].z;
        sO1[row*68 + c4 + 3] = o1r[k].w;
    }
    for (int i = t; i < 4096; i += 256) sFW[(i>>6)*65 + (i&63)] = fw[i];
    __syncthreads();
    // per-warp tail: LN -> FFN matvec -> softplus -> residual -> LN
    int w8 = wid;
    #pragma unroll 1
    for (int rr = 0; rr < 8; rr++){
        int rl = w8*8 + rr;
        float o0 = sO1[rl*68 + lane], o1 = sO1[rl*68 + lane + 32];
        float mean = wsum(o0+o1)*(1.f/64.f);
        float msq  = wsum(o0*o0+o1*o1)*(1.f/64.f);
        float rs = rsqrtf(msq - mean*mean + 1e-5f);
        sy[w8*64 + lane]    = (o0-mean)*rs*lng[lane]    + lnb[lane];
        sy[w8*64 + lane+32] = (o1-mean)*rs*lng[lane+32] + lnb[lane+32];
        __syncwarp();
        float a0 = fb[lane], a1 = fb[lane+32];
        #pragma unroll 8
        for (int c = 0; c < 64; c++){
            float yv = sy[w8*64 + c];
            a0 += yv * sFW[lane*65 + c];
            a1 += yv * sFW[(lane+32)*65 + c];
        }
        float s0 = o0 + softplus_fast(a0);
        float s1 = o1 + softplus_fast(a1);
        float m2 = wsum(s0+s1)*(1.f/64.f);
        float q2 = wsum(s0*s0+s1*s1)*(1.f/64.f);
        float r2 = rsqrtf(q2 - m2*m2 + 1e-5f);
        size_t m = qrow0 + (size_t)rl;
        outp[m*64 + lane]    = (s0-m2)*r2*lng[lane]    + lnb[lane];
        outp[m*64 + lane+32] = (s1-m2)*r2*lng[lane+32] + lnb[lane+32];
        __syncwarp();
    }
}

// ---------------- launch ----------------
extern "C" void kernel_launch(void* const* d_in, const int* in_sizes, int n_in,
                              void* d_out, int out_size){
    (void)in_sizes; (void)n_in; (void)out_size;
    const float* x     = (const float*)d_in[0];
    const float* wts   = (const float*)d_in[1];
    const float* ln_g  = (const float*)d_in[2];
    const float* ln_b  = (const float*)d_in[3];
    const float* wq_w  = (const float*)d_in[4];
    const float* wq_b  = (const float*)d_in[5];
    const float* wk_w  = (const float*)d_in[6];
    const float* wk_b  = (const float*)d_in[7];
    const float* wv_w  = (const float*)d_in[8];
    const float* wv_b  = (const float*)d_in[9];
    const float* mq_w  = (const float*)d_in[10];
    const float* mq_b  = (const float*)d_in[11];
    const float* mk_w  = (const float*)d_in[12];
    const float* mk_b  = (const float*)d_in[13];
    const float* out_w = (const float*)d_in[14];
    const float* out_b = (const float*)d_in[15];
    const float* ffn_w = (const float*)d_in[16];
    const float* ffn_b = (const float*)d_in[17];
    float* out = (float*)d_out;

    cudaFuncSetAttribute(k_attn, cudaFuncAttributeMaxDynamicSharedMemorySize, AT_SMEM);

    k_prep<<<2048 + 192, 256>>>(x, ln_g, ln_b, wq_w, wq_b, wk_w, wk_b, wv_w, wv_b,
                                mq_w, mq_b, mk_w, mk_b, out_w);
    k_qkv<<<dim3(ROWS/64, 3), 256>>>();
    k_attn<<<256, 256, AT_SMEM>>>(wts, x, out_b, ln_g, ln_b, ffn_w, ffn_b, out);
}

// round 16
// speedup vs baseline: 1.3133x; 1.0486x over previous
#include <cuda_runtime.h>
#include <cuda_fp16.h>
#include <cuda_bf16.h>
#include <math.h>
#include <stdint.h>

#define BB 8
#define NN 2048
#define EE 64
#define DD 256
#define ROWS (BB*NN)   // 16384

// ---------------- scratch (static device globals; no allocs) ----------------
__device__ __align__(16) __half g_xh[ROWS*EE];            // LN(x) in fp16
__device__ __align__(16) __half g_q[ROWS*DD];
__device__ __align__(16) __half g_k[ROWS*DD];
__device__ __align__(16) __nv_bfloat16 g_vo[ROWS*EE];     // V @ ow^T (+ ow@wvb), bf16
__device__ __align__(16) __half g_Wh[768*64];              // folded weights
__device__ float g_bp[768];

#define CEXP 0.18033688f   // 0.125 * log2(e)

// ---------------- generic helpers ----------------
__device__ __forceinline__ float wsum(float v){
    v += __shfl_xor_sync(0xffffffffu, v, 16);
    v += __shfl_xor_sync(0xffffffffu, v, 8);
    v += __shfl_xor_sync(0xffffffffu, v, 4);
    v += __shfl_xor_sync(0xffffffffu, v, 2);
    v += __shfl_xor_sync(0xffffffffu, v, 1);
    return v;
}
__device__ __forceinline__ uint32_t smem_u32(const void* p){
    uint32_t a;
    asm("{ .reg .u64 t; cvta.to.shared.u64 t, %1; cvt.u32.u64 %0, t; }" : "=r"(a) : "l"(p));
    return a;
}
__device__ __forceinline__ float ex2f(float x){
    float r;
    asm("ex2.approx.f32 %0, %1;" : "=f"(r) : "f"(x));
    return r;
}
__device__ __forceinline__ float lg2f(float x){
    float r;
    asm("lg2.approx.f32 %0, %1;" : "=f"(r) : "f"(x));
    return r;
}
__device__ __forceinline__ float softplus_fast(float x){
    if (x > 20.f) return x;
    return lg2f(1.f + ex2f(x * 1.44269504f)) * 0.69314718f;
}
__device__ __forceinline__ uint32_t packbf2(float a, float b){
    __nv_bfloat162 h = __floats2bfloat162_rn(a, b);
    return *(uint32_t*)&h;
}

// ---------------- cp.async helpers (sm_80+ baseline) ----------------
__device__ __forceinline__ void cpa16(uint32_t dst, const void* src){
    asm volatile("cp.async.cg.shared.global [%0], [%1], 16;" :: "r"(dst), "l"(src) : "memory");
}
__device__ __forceinline__ void cpa4(uint32_t dst, const void* src){
    asm volatile("cp.async.ca.shared.global [%0], [%1], 4;" :: "r"(dst), "l"(src) : "memory");
}
#define CPA_COMMIT() asm volatile("cp.async.commit_group;" ::: "memory")
#define CPA_WAIT(n)  asm volatile("cp.async.wait_group %0;" :: "n"(n) : "memory")

// ---------------- mma.sync / ldmatrix helpers (baseline PTX, sm_80+) --------
__device__ __forceinline__ void ldm_x4(uint32_t a[4], uint32_t addr){
    asm volatile("ldmatrix.sync.aligned.m8n8.x4.shared.b16 {%0,%1,%2,%3}, [%4];"
        : "=r"(a[0]), "=r"(a[1]), "=r"(a[2]), "=r"(a[3]) : "r"(addr));
}
__device__ __forceinline__ void ldm_x4t(uint32_t a[4], uint32_t addr){
    asm volatile("ldmatrix.sync.aligned.m8n8.x4.trans.shared.b16 {%0,%1,%2,%3}, [%4];"
        : "=r"(a[0]), "=r"(a[1]), "=r"(a[2]), "=r"(a[3]) : "r"(addr));
}
__device__ __forceinline__ void mma16816(float c[4], const uint32_t a[4], const uint32_t b[2]){
    asm volatile("mma.sync.aligned.m16n8k16.row.col.f32.f16.f16.f32 "
        "{%0,%1,%2,%3}, {%4,%5,%6,%7}, {%8,%9}, {%0,%1,%2,%3};"
        : "+f"(c[0]), "+f"(c[1]), "+f"(c[2]), "+f"(c[3])
        : "r"(a[0]), "r"(a[1]), "r"(a[2]), "r"(a[3]), "r"(b[0]), "r"(b[1]));
}
__device__ __forceinline__ void mma16816bf(float c[4], const uint32_t a[4], const uint32_t b[2]){
    asm volatile("mma.sync.aligned.m16n8k16.row.col.f32.bf16.bf16.f32 "
        "{%0,%1,%2,%3}, {%4,%5,%6,%7}, {%8,%9}, {%0,%1,%2,%3};"
        : "+f"(c[0]), "+f"(c[1]), "+f"(c[2]), "+f"(c[3])
        : "r"(a[0]), "r"(a[1]), "r"(a[2]), "r"(a[3]), "r"(b[0]), "r"(b[1]));
}

// ---------------- k_prep: LN (blocks 0..2047) + parallel fold (2048..2815) --
__global__ __launch_bounds__(256) void k_prep(const float* __restrict__ x,
                       const float* __restrict__ g, const float* __restrict__ be,
                       const float* __restrict__ wq_w, const float* __restrict__ wq_b,
                       const float* __restrict__ wk_w, const float* __restrict__ wk_b,
                       const float* __restrict__ wv_w, const float* __restrict__ wv_b,
                       const float* __restrict__ mq_w, const float* __restrict__ mq_b,
                       const float* __restrict__ mk_w, const float* __restrict__ mk_b,
                       const float* __restrict__ ow){
    int t = threadIdx.x;
    if (blockIdx.x < 2048){
        int lane = t & 31, w = t >> 5;
        size_t row = (size_t)blockIdx.x*8 + w;
        const float* xr = x + row*64;
        float x0 = xr[lane], x1 = xr[lane+32];
        float mean = wsum(x0+x1)*(1.f/64.f);
        float msq  = wsum(x0*x0+x1*x1)*(1.f/64.f);
        float rs = rsqrtf(msq - mean*mean + 1e-5f);
        __half* o = g_xh + row*64;
        o[lane]    = __float2half_rn((x0-mean)*rs*g[lane]    + be[lane]);
        o[lane+32] = __float2half_rn((x1-mean)*rs*g[lane+32] + be[lane+32]);
        return;
    }
    // ---- fold: one block per output row r ----
    __shared__ float sm_m[256];
    __shared__ float sm_p[256];   // partials: [cq][e]
    __shared__ float sm_b[8];
    int r = blockIdx.x - 2048;
    if (r >= 576){
        if (t < 64) g_Wh[r*64 + t] = __float2half_rn(0.f);
        if (t == 0) g_bp[r] = 0.f;
        return;
    }
    const float* mrow;     // 256-wide combining row
    const float* wmat;     // [256][64]
    const float* bvec;     // 256-wide bias (or null -> 0)
    float bself = 0.f;
    if (r < 256){
        mrow = mq_w + (size_t)r*256; wmat = wq_w; bvec = wq_b; bself = mq_b[r];
    } else if (r < 512){
        mrow = mk_w + (size_t)(r-256)*256; wmat = wk_w; bvec = wk_b; bself = mk_b[r-256];
    } else {
        mrow = ow + (size_t)(r-512)*256; wmat = wv_w; bvec = wv_b; bself = 0.f;
    }
    float mv = mrow[t];
    sm_m[t] = mv;
    float pb = mv * bvec[t];
    __syncthreads();
    int e = t & 63, cq = t >> 6;
    float acc = 0.f;
    #pragma unroll 8
    for (int j = 0; j < 64; j++){
        int c = cq*64 + j;
        acc += sm_m[c] * wmat[(size_t)c*64 + e];
    }
    sm_p[t] = acc;
    // bias reduce
    float pbw = wsum(pb);
    if ((t & 31) == 0) sm_b[t >> 5] = pbw;
    __syncthreads();
    if (t < 64){
        float v = sm_p[t] + sm_p[64+t] + sm_p[128+t] + sm_p[192+t];
        g_Wh[r*64 + t] = __float2half_rn(v);
    }
    if (t == 0){
        float bb = bself;
        #pragma unroll
        for (int i = 0; i < 8; i++) bb += sm_b[i];
        g_bp[r] = bb;
    }
}

// ---------------- k_qkv: HMMA GEMM, grid (256,3): y=0 Q, y=1 K, y=2 Vo -------
__global__ __launch_bounds__(256) void k_qkv(){
    __shared__ __half sA[64*72];    // pitch 144 B
    __shared__ __half sB[256*72];
    int t = threadIdx.x, lane = t & 31, wid = t >> 5;
    int t4 = lane & 3, gq = lane >> 2;
    int wq = wid & 1, wd = wid >> 1;
    int m0 = blockIdx.x*64;
    int ny = blockIdx.y;
    uint32_t sa = smem_u32(sA), sbb = smem_u32(sB);
    for (int i = t; i < 512; i += 256){
        int r = i >> 3, c = i & 7;
        *(uint4*)((char*)sA + r*144 + c*16) =
            *(const uint4*)((const char*)(g_xh + ((size_t)(m0+r))*64) + c*16);
    }
    for (int i = t; i < 2048; i += 256){
        int r = i >> 3, c = i & 7;
        *(uint4*)((char*)sB + r*144 + c*16) =
            *(const uint4*)((const char*)(g_Wh + (size_t)(ny*256 + r)*64) + c*16);
    }
    __syncthreads();
    uint32_t lo16 = lane & 15, hi16 = lane >> 4;
    uint32_t aQb = sa + (uint32_t)(wq*32 + lo16)*144 + hi16*16;
    uint32_t kl  = (uint32_t)((lane & 7) + ((lane >> 4) << 3));
    uint32_t bWb = sbb + (uint32_t)(wd*64)*144 + kl*144 + (uint32_t)((lane >> 3) & 1)*16;

    float out[2][8][4] = {};
    #pragma unroll
    for (int ks = 0; ks < 4; ks++){
        uint32_t hk = (uint32_t)ks*32;
        uint32_t aq[2][4];
        ldm_x4(aq[0], aQb + hk);
        ldm_x4(aq[1], aQb + 16u*144 + hk);
        #pragma unroll
        for (int ng = 0; ng < 4; ng++){
            uint32_t kf[4];
            ldm_x4(kf, bWb + (uint32_t)(ng*16)*144 + hk);
            #pragma unroll
            for (int mb = 0; mb < 2; mb++){
                mma16816(out[mb][ng*2],   aq[mb], kf);
                mma16816(out[mb][ng*2+1], aq[mb], kf+2);
            }
        }
    }
    const float* bp = g_bp + ny*256;
    if (ny < 2){
        __half* dst = (ny == 0) ? g_q : g_k;
        #pragma unroll
        for (int mb = 0; mb < 2; mb++){
            size_t rA = (size_t)m0 + (size_t)(wq*32 + mb*16 + gq);
            size_t rB = rA + 8;
            #pragma unroll
            for (int nt = 0; nt < 8; nt++){
                int col = wd*64 + nt*8 + 2*t4;
                float b0 = bp[col], b1 = bp[col+1];
                __half2 hA = __floats2half2_rn(out[mb][nt][0] + b0, out[mb][nt][1] + b1);
                __half2 hB = __floats2half2_rn(out[mb][nt][2] + b0, out[mb][nt][3] + b1);
                *(__half2*)&dst[rA*256 + col] = hA;
                *(__half2*)&dst[rB*256 + col] = hB;
            }
        }
    } else if (wd == 0){
        #pragma unroll
        for (int mb = 0; mb < 2; mb++){
            size_t rA = (size_t)m0 + (size_t)(wq*32 + mb*16 + gq);
            size_t rB = rA + 8;
            #pragma unroll
            for (int nt = 0; nt < 8; nt++){
                int col = nt*8 + 2*t4;
                float b0 = bp[col], b1 = bp[col+1];
                uint32_t pA = packbf2(out[mb][nt][0] + b0, out[mb][nt][1] + b1);
                uint32_t pB = packbf2(out[mb][nt][2] + b0, out[mb][nt][3] + b1);
                *(uint32_t*)&g_vo[rA*64 + col] = pA;
                *(uint32_t*)&g_vo[rB*64 + col] = pB;
            }
        }
    }
}

// ---------------- k_attn: fused score+softmax+AV + residual/LN/FFN tail -----
// 256 threads = 8 warps: wq = wid&1 (32-row group), wh = wid>>1 (head 0..3)
#define AT_SQO 0
#define AT_SK0 33792
#define AT_SK1 50688
#define AT_SV0 67584
#define AT_SV1 72192
#define AT_SW0 76800
#define AT_SW1 76928
#define AT_SLO 77056
#define AT_SLW 78080
#define AT_SMEM 79104
#define EP_O1  0
#define EP_FW  17408
#define EP_SY  34048

__global__ void __launch_bounds__(256,2) k_attn(const float* __restrict__ gw,
                                                const float* __restrict__ xin,
                                                const float* __restrict__ ob,
                                                const float* __restrict__ lng,
                                                const float* __restrict__ lnb,
                                                const float* __restrict__ fw,
                                                const float* __restrict__ fb,
                                                float* __restrict__ outp){
    extern __shared__ char sm[];
    uint32_t sb = smem_u32(sm);
    int t = threadIdx.x, lane = t & 31, wid = t >> 5;
    int t4 = lane & 3, gq = lane >> 2;
    int wq = wid & 1, wh = wid >> 1;
    int b = blockIdx.x >> 5, qt = blockIdx.x & 31;
    size_t qrow0 = (size_t)b*NN + (size_t)qt*64;
    const char*  qg  = (const char*)(g_q + qrow0*256);
    const char*  kgb = (const char*)(g_k + (size_t)b*NN*256);
    const char*  vgb = (const char*)(g_vo + (size_t)b*NN*64);
    const float* wb  = gw + (size_t)b*NN;
    float* sL = (float*)(sm + AT_SLO);
    float* sLW = (float*)(sm + AT_SLW);

    for (int i = t; i < 1024; i += 256){
        int r = i >> 5, c = i & 31;
        cpa16(sb + AT_SK0 + r*528 + c*16, kgb + (size_t)r*512 + c*16);
    }
    {
        int r = t >> 3, c = t & 7;
        cpa16(sb + AT_SV0 + r*144 + c*16, vgb + (size_t)r*128 + c*16);
    }
    if (t < 32) cpa4(sb + AT_SW0 + t*4, wb + t);
    CPA_COMMIT();
    for (int i = t; i < 2048; i += 256){
        int r = i >> 5, c = i & 31;
        *(uint4*)(sm + AT_SQO + r*528 + c*16) = *(const uint4*)(qg + r*512 + c*16);
    }

    uint32_t lo16 = lane & 15, hi16 = lane >> 4;
    uint32_t aQb = sb + AT_SQO + (uint32_t)(wq*32 + lo16)*528 + hi16*16;
    uint32_t kl  = (uint32_t)((lane & 7) + ((lane >> 4) << 3));

    float out[2][8][4];
    #pragma unroll
    for (int mb = 0; mb < 2; mb++)
        #pragma unroll
        for (int nt = 0; nt < 8; nt++)
            #pragma unroll
            for (int q = 0; q < 4; q++) out[mb][nt][q] = 0.f;
    float lacc[2][2], lwac[2][2];
    #pragma unroll
    for (int mb = 0; mb < 2; mb++)
        #pragma unroll
        for (int hf = 0; hf < 2; hf++){ lacc[mb][hf] = 0.f; lwac[mb][hf] = 0.f; }

    for (int jt = 0; jt < 64; jt++){
        uint32_t koff = (jt & 1) ? AT_SK1 : AT_SK0;
        uint32_t voff = (jt & 1) ? AT_SV1 : AT_SV0;
        uint32_t woff = (jt & 1) ? AT_SW1 : AT_SW0;
        if (jt < 63){
            uint32_t kn = (jt & 1) ? AT_SK0 : AT_SK1;
            uint32_t vn = (jt & 1) ? AT_SV0 : AT_SV1;
            uint32_t wn = (jt & 1) ? AT_SW0 : AT_SW1;
            const char* ksrc = kgb + (size_t)(jt+1)*16384;
            const char* vsrc = vgb + (size_t)(jt+1)*4096;
            for (int i = t; i < 1024; i += 256){
                int r = i >> 5, c = i & 31;
                cpa16(sb + kn + r*528 + c*16, ksrc + (size_t)r*512 + c*16);
            }
            {
                int r = t >> 3, c = t & 7;
                cpa16(sb + vn + r*144 + c*16, vsrc + (size_t)r*128 + c*16);
            }
            if (t < 32) cpa4(sb + wn + t*4, wb + (jt+1)*32 + t);
            CPA_COMMIT();
            CPA_WAIT(1);
        } else {
            CPA_WAIT(0);
        }
        __syncthreads();
        const float* sw = (const float*)(sm + woff);
        uint32_t bK = sb + koff + kl*528 + (uint32_t)((lane >> 3) & 1)*16;
        uint32_t bV = sb + voff + lo16*144 + hi16*16;

        float sacc[2][2][2][4];   // [kb][mb][nt][4]
        #pragma unroll
        for (int kb = 0; kb < 2; kb++)
            #pragma unroll
            for (int mb = 0; mb < 2; mb++)
                #pragma unroll
                for (int nt = 0; nt < 2; nt++)
                    #pragma unroll
                    for (int q = 0; q < 4; q++) sacc[kb][mb][nt][q] = 0.f;
        #pragma unroll
        for (int ks = 0; ks < 4; ks++){
            uint32_t hk = (uint32_t)(wh*64 + ks*16)*2;
            uint32_t aq0[4], aq1[4];
            ldm_x4(aq0, aQb + hk);
            ldm_x4(aq1, aQb + 16u*528 + hk);
            #pragma unroll
            for (int kb = 0; kb < 2; kb++){
                uint32_t kf[4];
                ldm_x4(kf, bK + (uint32_t)(kb*16)*528 + hk);
                mma16816(sacc[kb][0][0], aq0, kf);
                mma16816(sacc[kb][0][1], aq0, kf+2);
                mma16816(sacc[kb][1][0], aq1, kf);
                mma16816(sacc[kb][1][1], aq1, kf+2);
            }
        }
        #pragma unroll
        for (int kb = 0; kb < 2; kb++){
            float wv[4], mv[4];
            #pragma unroll
            for (int nt = 0; nt < 2; nt++){
                int kloc = kb*16 + nt*8 + 2*t4;
                wv[2*nt]   = sw[kloc];
                wv[2*nt+1] = sw[kloc+1];
                mv[2*nt]   = (wv[2*nt]   != 0.f) ? 1.f : 0.f;
                mv[2*nt+1] = (wv[2*nt+1] != 0.f) ? 1.f : 0.f;
            }
            uint32_t pk2[2][4];
            #pragma unroll
            for (int mb = 0; mb < 2; mb++){
                #pragma unroll
                for (int nt = 0; nt < 2; nt++){
                    float e0 = ex2f(sacc[kb][mb][nt][0]*CEXP);
                    float e1 = ex2f(sacc[kb][mb][nt][1]*CEXP);
                    float e2 = ex2f(sacc[kb][mb][nt][2]*CEXP);
                    float e3 = ex2f(sacc[kb][mb][nt][3]*CEXP);
                    lacc[mb][0] = fmaf(e0, mv[2*nt], fmaf(e1, mv[2*nt+1], lacc[mb][0]));
                    lacc[mb][1] = fmaf(e2, mv[2*nt], fmaf(e3, mv[2*nt+1], lacc[mb][1]));
                    float ew0 = e0*wv[2*nt], ew1 = e1*wv[2*nt+1];
                    float ew2 = e2*wv[2*nt], ew3 = e3*wv[2*nt+1];
                    lwac[mb][0] += ew0 + ew1;
                    lwac[mb][1] += ew2 + ew3;
                    pk2[mb][nt*2]   = packbf2(ew0, ew1);
                    pk2[mb][nt*2+1] = packbf2(ew2, ew3);
                }
            }
            #pragma unroll
            for (int dt2 = 0; dt2 < 4; dt2++){
                uint32_t vf[4];
                ldm_x4t(vf, bV + (uint32_t)(kb*16)*144 + (uint32_t)dt2*32);
                mma16816bf(out[0][dt2*2],   pk2[0], vf);
                mma16816bf(out[0][dt2*2+1], pk2[0], vf+2);
                mma16816bf(out[1][dt2*2],   pk2[1], vf);
                mma16816bf(out[1][dt2*2+1], pk2[1], vf+2);
            }
        }
        __syncthreads();
    }
    #pragma unroll
    for (int mb = 0; mb < 2; mb++)
        #pragma unroll
        for (int hf = 0; hf < 2; hf++){
            float v = lacc[mb][hf];
            v += __shfl_xor_sync(0xffffffffu, v, 1);
            v += __shfl_xor_sync(0xffffffffu, v, 2);
            float u = lwac[mb][hf];
            u += __shfl_xor_sync(0xffffffffu, u, 1);
            u += __shfl_xor_sync(0xffffffffu, u, 2);
            if (t4 == 0){
                int row = wq*32 + mb*16 + hf*8 + gq;
                sL[row*4 + wh] = v;
                sLW[row*4 + wh] = u;
            }
        }
    __syncthreads();
    float* red = (float*)sm;
    #pragma unroll
    for (int mb = 0; mb < 2; mb++){
        int rA = wq*32 + mb*16 + gq;
        int rB = rA + 8;
        float ilA = 1.f / sL[rA*4 + wh];
        float ilB = 1.f / sL[rB*4 + wh];
        #pragma unroll
        for (int nt = 0; nt < 8; nt++){
            int col = nt*8 + 2*t4;
            *(float2*)&red[(wh*64 + rA)*64 + col] = make_float2(out[mb][nt][0]*ilA, out[mb][nt][1]*ilA);
            *(float2*)&red[(wh*64 + rB)*64 + col] = make_float2(out[mb][nt][2]*ilB, out[mb][nt][3]*ilB);
        }
    }
    __syncthreads();
    float4 o1r[4];
    int rows4[4], cols4[4];
    #pragma unroll
    for (int k = 0; k < 4; k++){
        int i = t + k*256;
        int row = i >> 4, c4 = (i & 15)*4;
        rows4[k] = row; cols4[k] = c4;
        float4 s0 = *(const float4*)&red[(row)*64 + c4];
        float4 s1 = *(const float4*)&red[(64 + row)*64 + c4];
        float4 s2 = *(const float4*)&red[(128 + row)*64 + c4];
        float4 s3 = *(const float4*)&red[(192 + row)*64 + c4];
        float z = sLW[row*4+0]/sL[row*4+0] + sLW[row*4+1]/sL[row*4+1]
                + sLW[row*4+2]/sL[row*4+2] + sLW[row*4+3]/sL[row*4+3];
        float iz = 1.f / z;
        float4 xv = *(const float4*)&xin[(qrow0 + (size_t)row)*64 + c4];
        float4 obv = *(const float4*)&ob[c4];
        o1r[k] = make_float4((s0.x+s1.x+s2.x+s3.x)*iz + xv.x + obv.x,
                             (s0.y+s1.y+s2.y+s3.y)*iz + xv.y + obv.y,
                             (s0.z+s1.z+s2.z+s3.z)*iz + xv.z + obv.z,
                             (s0.w+s1.w+s2.w+s3.w)*iz + xv.w + obv.w);
    }
    __syncthreads();
    float* sO1 = (float*)(sm + EP_O1);
    float* sFW = (float*)(sm + EP_FW);
    float* sy  = (float*)(sm + EP_SY);
    #pragma unroll
    for (int k = 0; k < 4; k++){
        int row = rows4[k], c4 = cols4[k];
        sO1[row*68 + c4 + 0] = o1r[k].x;
        sO1[row*68 + c4 + 1] = o1r[k].y;
        sO1[row*68 + c4 + 2] = o1r[k].z;
        sO1[row*68 + c4 + 3] = o1r[k].w;
    }
    for (int i = t; i < 4096; i += 256) sFW[(i>>6)*65 + (i&63)] = fw[i];
    __syncthreads();
    int w8 = wid;
    #pragma unroll 1
    for (int rr = 0; rr < 8; rr++){
        int rl = w8*8 + rr;
        float o0 = sO1[rl*68 + lane], o1 = sO1[rl*68 + lane + 32];
        float mean = wsum(o0+o1)*(1.f/64.f);
        float msq  = wsum(o0*o0+o1*o1)*(1.f/64.f);
        float rs = rsqrtf(msq - mean*mean + 1e-5f);
        sy[w8*64 + lane]    = (o0-mean)*rs*lng[lane]    + lnb[lane];
        sy[w8*64 + lane+32] = (o1-mean)*rs*lng[lane+32] + lnb[lane+32];
        __syncwarp();
        float a0 = fb[lane], a1 = fb[lane+32];
        #pragma unroll 8
        for (int c = 0; c < 64; c++){
            float yv = sy[w8*64 + c];
            a0 += yv * sFW[lane*65 + c];
            a1 += yv * sFW[(lane+32)*65 + c];
        }
        float s0 = o0 + softplus_fast(a0);
        float s1 = o1 + softplus_fast(a1);
        float m2 = wsum(s0+s1)*(1.f/64.f);
        float q2 = wsum(s0*s0+s1*s1)*(1.f/64.f);
        float r2 = rsqrtf(q2 - m2*m2 + 1e-5f);
        size_t m = qrow0 + (size_t)rl;
        outp[m*64 + lane]    = (s0-m2)*r2*lng[lane]    + lnb[lane];
        outp[m*64 + lane+32] = (s1-m2)*r2*lng[lane+32] + lnb[lane+32];
        __syncwarp();
    }
}

// ---------------- launch ----------------
extern "C" void kernel_launch(void* const* d_in, const int* in_sizes, int n_in,
                              void* d_out, int out_size){
    (void)in_sizes; (void)n_in; (void)out_size;
    const float* x     = (const float*)d_in[0];
    const float* wts   = (const float*)d_in[1];
    const float* ln_g  = (const float*)d_in[2];
    const float* ln_b  = (const float*)d_in[3];
    const float* wq_w  = (const float*)d_in[4];
    const float* wq_b  = (const float*)d_in[5];
    const float* wk_w  = (const float*)d_in[6];
    const float* wk_b  = (const float*)d_in[7];
    const float* wv_w  = (const float*)d_in[8];
    const float* wv_b  = (const float*)d_in[9];
    const float* mq_w  = (const float*)d_in[10];
    const float* mq_b  = (const float*)d_in[11];
    const float* mk_w  = (const float*)d_in[12];
    const float* mk_b  = (const float*)d_in[13];
    const float* out_w = (const float*)d_in[14];
    const float* out_b = (const float*)d_in[15];
    const float* ffn_w = (const float*)d_in[16];
    const float* ffn_b = (const float*)d_in[17];
    float* out = (float*)d_out;

    cudaFuncSetAttribute(k_attn, cudaFuncAttributeMaxDynamicSharedMemorySize, AT_SMEM);

    k_prep<<<2048 + 768, 256>>>(x, ln_g, ln_b, wq_w, wq_b, wk_w, wk_b, wv_w, wv_b,
                                mq_w, mq_b, mk_w, mk_b, out_w);
    k_qkv<<<dim3(ROWS/64, 3), 256>>>();
    k_attn<<<256, 256, AT_SMEM>>>(wts, x, out_b, ln_g, ln_b, ffn_w, ffn_b, out);
}